// round 11
// baseline (speedup 1.0000x reference)
#include <cuda_runtime.h>
#include <cuda_fp16.h>
#include <cuda_bf16.h>
#include <math.h>
#include <stdint.h>

#define NB 2
#define NN 256
#define DD 256
#define NH 8
#define FFD 1024

// ---------------- scratch (static device globals) ----------------
__device__ float g_x [NB*NN*DD];
__device__ float g_nq[NB*NN*DD];
__device__ float g_sc[(size_t)NB*NH*NN*NN];
__device__ float g_ao[NB*NN*DD];
__device__ float g_r [NB*NN*DD];
__device__ float g_x2[NB*NN*DD];
__device__ float g_hg[NB*NN*FFD];
__device__ __half g_wh[DD*DD];   // W^T hi plane  [n][k]
__device__ __half g_wl[DD*DD];   // W^T lo plane  [n][k]

// ---------------- PTX helpers ----------------
__device__ __forceinline__ uint32_t smem_u32(const void* p) {
    uint32_t a;
    asm("{ .reg .u64 t; cvta.to.shared.u64 t, %1; cvt.u32.u64 %0, t; }" : "=r"(a) : "l"(p));
    return a;
}
#define CP16(dst, src) \
    asm volatile("cp.async.cg.shared.global [%0], [%1], 16;" :: "r"(dst), "l"(src))
#define CP_COMMIT() asm volatile("cp.async.commit_group;" ::: "memory")
#define CP_WAIT0() asm volatile("cp.async.wait_group 0;" ::: "memory")
#define CP_WAIT1() asm volatile("cp.async.wait_group 1;" ::: "memory")
#define CP_WAIT2() asm volatile("cp.async.wait_group 2;" ::: "memory")

#define LDMX4(r, a) \
    asm volatile("ldmatrix.sync.aligned.m8n8.x4.shared.b16 {%0,%1,%2,%3}, [%4];" \
        : "=r"((r)[0]), "=r"((r)[1]), "=r"((r)[2]), "=r"((r)[3]) : "r"(a))

__device__ __forceinline__ void mma16816(float* acc, const uint32_t* a,
                                         uint32_t b0, uint32_t b1) {
    asm volatile(
        "mma.sync.aligned.m16n8k16.row.col.f32.f16.f16.f32 "
        "{%0,%1,%2,%3}, {%4,%5,%6,%7}, {%8,%9}, {%0,%1,%2,%3};"
        : "+f"(acc[0]), "+f"(acc[1]), "+f"(acc[2]), "+f"(acc[3])
        : "r"(a[0]), "r"(a[1]), "r"(a[2]), "r"(a[3]), "r"(b0), "r"(b1));
}

__device__ __forceinline__ uint32_t packh(__half a, __half b) {
    __half2 h = __halves2half2(a, b);
    return *(uint32_t*)&h;
}

// ---------------- prep W: plain fp16 hi/lo planes of W^T [n][k] ------------
__global__ void prep_w(const float* __restrict__ W,
                       __half* __restrict__ wh, __half* __restrict__ wl) {
    int id = blockIdx.x * 256 + threadIdx.x;   // 65536
    int n = id >> 8, k = id & 255;
    float v = W[k * 256 + n];
    __half h = __float2half_rn(v);
    wh[id] = h;
    wl[id] = __float2half_rn(v - __half2float(h));
}

// ---------------- fused edge GEMM (ldmatrix + mma fp16x3) ------------------
// grid (jt=2, i=256, b=2), 512 threads (16 warps). CTA: 128 rows x 256 cols.
// Warp (wr=w&3, wc=w>>2): rows wr*32..+31 (2 m16 tiles), cols wc*64..+63.
// k-chunks of 32 (8 chunks), 3-stage cp.async pipeline.
#define A32_OFF   0            // 3 stages x 128 rows x 144B = 55296
#define A32_ST    18432
#define A16_OFF   55296        // 2 bufs x 2 planes x 128 x 80B = 40960
#define A16_BUF   20480
#define B_OFF     96256        // 3 stages x 2 planes x 256 x 80B = 122880
#define B_ST      40960
#define MISC      219136
#define EDGE_SMEM 221184

__global__ __launch_bounds__(512, 1) void edge_mma_kernel(
    const float* __restrict__ edges,
    const __half* __restrict__ whp, const __half* __restrict__ wlp,
    const float* __restrict__ bias, const float* __restrict__ nq,
    float* __restrict__ scores) {
    extern __shared__ char smem[];
    const uint32_t sb = smem_u32(smem);
    const int t = threadIdx.x, lane = t & 31, w = t >> 5;
    const int qp = lane & 3, lg = lane >> 2;
    const int wr = w & 3, wc = w >> 2;
    const int jt = blockIdx.x, i = blockIdx.y, b = blockIdx.z;
    const size_t r0 = ((size_t)(b * NN + i)) * NN + jt * 128;
    const char* eg = (const char*)(edges + r0 * DD);
    const char* whg = (const char*)whp;
    const char* wlg = (const char*)wlp;

    // per-lane ldmatrix offsets
    const uint32_t aoff = (lane & 15) * 80 + (lane >> 4) * 16;
    const uint32_t boff = (((lane >> 4) << 3) + (lane & 7)) * 80 + ((lane >> 3) & 1) * 16;

    // stage bias + nq_i in misc
    float* sBias = (float*)(smem + MISC);
    float* sNqi  = sBias + 256;
    if (t < 256) {
        sBias[t] = bias[t];
        sNqi[t]  = nq[((size_t)(b * NN + i)) * DD + t];
    }

    // prologue: issue chunks 0,1,2 into stages 0,1,2
    #pragma unroll
    for (int c = 0; c < 3; ++c) {
        #pragma unroll
        for (int it = 0; it < 2; ++it) {
            int u = t + 512 * it, row = u >> 3, part = u & 7;
            CP16(sb + A32_OFF + c * A32_ST + row * 144 + part * 16,
                 eg + (size_t)row * 1024 + c * 128 + part * 16);
        }
        #pragma unroll
        for (int pl = 0; pl < 2; ++pl) {
            const char* wsrc = pl ? wlg : whg;
            #pragma unroll
            for (int it = 0; it < 2; ++it) {
                int u = t + 512 * it, n = u >> 2, part = u & 3;
                CP16(sb + B_OFF + c * B_ST + pl * 20480 + n * 80 + part * 16,
                     wsrc + n * 512 + c * 64 + part * 16);
            }
        }
        CP_COMMIT();
    }

    float acc[64];
    #pragma unroll
    for (int q = 0; q < 64; ++q) acc[q] = 0.f;

    const int cvrow = t >> 2, cvks = (t & 3) * 8;

    int st = 0;
    #pragma unroll 1
    for (int c = 0; c < 8; ++c) {
        if (c < 6) { CP_WAIT2(); } else if (c == 6) { CP_WAIT1(); } else { CP_WAIT0(); }
        __syncthreads();

        // ---- convert A fp32 -> fp16 hi/lo planes (each element once) ----
        {
            const char* a32 = smem + A32_OFF + st * A32_ST + cvrow * 144 + cvks * 4;
            float4 f0 = *(const float4*)(a32);
            float4 f1 = *(const float4*)(a32 + 16);
            float fv[8] = { f0.x, f0.y, f0.z, f0.w, f1.x, f1.y, f1.z, f1.w };
            __half h[8], l[8];
            #pragma unroll
            for (int q = 0; q < 8; ++q) {
                h[q] = __float2half_rn(fv[q]);
                l[q] = __float2half_rn(fv[q] - __half2float(h[q]));
            }
            uint4 H, L;
            H.x = packh(h[0], h[1]); H.y = packh(h[2], h[3]);
            H.z = packh(h[4], h[5]); H.w = packh(h[6], h[7]);
            L.x = packh(l[0], l[1]); L.y = packh(l[2], l[3]);
            L.z = packh(l[4], l[5]); L.w = packh(l[6], l[7]);
            char* dhi = smem + A16_OFF + (c & 1) * A16_BUF + cvrow * 80 + cvks * 2;
            *(uint4*)dhi = H;
            *(uint4*)(dhi + 10240) = L;
        }
        __syncthreads();

        // ---- MMA phase: 2 k16 steps ----
        const uint32_t abase = sb + A16_OFF + (c & 1) * A16_BUF + wr * 32 * 80 + aoff;
        const uint32_t bbase = sb + B_OFF + st * B_ST + wc * 64 * 80 + boff;
        #pragma unroll
        for (int s = 0; s < 2; ++s) {
            const uint32_t k2 = s * 32;
            uint32_t AH[2][4], AL[2][4], B4[4][4];
            LDMX4(AH[0], abase + k2);
            LDMX4(AH[1], abase + 16 * 80 + k2);
            LDMX4(AL[0], abase + 10240 + k2);
            LDMX4(AL[1], abase + 10240 + 16 * 80 + k2);
            #pragma unroll
            for (int g = 0; g < 4; ++g) LDMX4(B4[g], bbase + g * 16 * 80 + k2);
            #pragma unroll
            for (int g = 0; g < 4; ++g) {
                #pragma unroll
                for (int m = 0; m < 2; ++m) {
                    mma16816(&acc[(m * 8 + 2 * g) * 4],     AH[m], B4[g][0], B4[g][1]);
                    mma16816(&acc[(m * 8 + 2 * g + 1) * 4], AH[m], B4[g][2], B4[g][3]);
                    mma16816(&acc[(m * 8 + 2 * g) * 4],     AL[m], B4[g][0], B4[g][1]);
                    mma16816(&acc[(m * 8 + 2 * g + 1) * 4], AL[m], B4[g][2], B4[g][3]);
                }
            }
            #pragma unroll
            for (int g = 0; g < 4; ++g) LDMX4(B4[g], bbase + 20480 + g * 16 * 80 + k2);
            #pragma unroll
            for (int g = 0; g < 4; ++g) {
                #pragma unroll
                for (int m = 0; m < 2; ++m) {
                    mma16816(&acc[(m * 8 + 2 * g) * 4],     AH[m], B4[g][0], B4[g][1]);
                    mma16816(&acc[(m * 8 + 2 * g + 1) * 4], AH[m], B4[g][2], B4[g][3]);
                }
            }
        }
        __syncthreads();

        // ---- issue chunk c+3 into stage st ----
        if (c + 3 < 8) {
            const int cn = c + 3;
            #pragma unroll
            for (int it = 0; it < 2; ++it) {
                int u = t + 512 * it, row = u >> 3, part = u & 7;
                CP16(sb + A32_OFF + st * A32_ST + row * 144 + part * 16,
                     eg + (size_t)row * 1024 + cn * 128 + part * 16);
            }
            #pragma unroll
            for (int pl = 0; pl < 2; ++pl) {
                const char* wsrc = pl ? wlg : whg;
                #pragma unroll
                for (int it = 0; it < 2; ++it) {
                    int u = t + 512 * it, n = u >> 2, part = u & 3;
                    CP16(sb + B_OFF + st * B_ST + pl * 20480 + n * 80 + part * 16,
                         wsrc + n * 512 + cn * 64 + part * 16);
                }
            }
            CP_COMMIT();
        }
        if (++st == 3) st = 0;
    }

    // ---- epilogue: per-head score reduction (layout identical to R10) ----
    const float* nqb = nq + ((size_t)b * NN) * DD;
    const float invs = 0.17677669529663687f;   // 1/sqrt(32)
    #pragma unroll
    for (int m = 0; m < 2; ++m) {
        const int jb = jt * 128 + wr * 32 + m * 16 + lg;
        #pragma unroll
        for (int hh = 0; hh < 2; ++hh) {
            const int h = wc * 2 + hh;
            float s1 = 0.f, s2 = 0.f;
            #pragma unroll
            for (int k = 0; k < 4; ++k) {
                const int nt = hh * 4 + k;
                const int col = wc * 64 + nt * 8 + qp * 2;
                const float* a = &acc[(m * 8 + nt) * 4];
                float2 q1 = *(const float2*)(nqb + (size_t)jb * DD + col);
                float2 q2 = *(const float2*)(nqb + (size_t)(jb + 8) * DD + col);
                float bi0 = sBias[col], bi1 = sBias[col + 1];
                float ni0 = sNqi[col],  ni1 = sNqi[col + 1];
                float e;
                e = a[0] + bi0; s1 += (e + ni0) * (e + q1.x);
                e = a[1] + bi1; s1 += (e + ni1) * (e + q1.y);
                e = a[2] + bi0; s2 += (e + ni0) * (e + q2.x);
                e = a[3] + bi1; s2 += (e + ni1) * (e + q2.y);
            }
            s1 += __shfl_xor_sync(0xffffffffu, s1, 1);
            s1 += __shfl_xor_sync(0xffffffffu, s1, 2);
            s2 += __shfl_xor_sync(0xffffffffu, s2, 1);
            s2 += __shfl_xor_sync(0xffffffffu, s2, 2);
            if (qp == 0) {
                float* sp = scores + (((size_t)(b * NH + h)) << 16) + (size_t)i * NN;
                sp[jb]     = 10.0f * tanhf(s1 * invs);
                sp[jb + 8] = 10.0f * tanhf(s2 * invs);
            }
        }
    }
}

// ---------------- LayerNorm ----------------
__global__ void ln_kernel(const float* __restrict__ in,
                          const float* __restrict__ gam,
                          const float* __restrict__ bet,
                          float* __restrict__ out) {
    __shared__ float sh[16];
    __shared__ float stats[2];
    const int row = blockIdx.x, t = threadIdx.x;
    float v = in[(size_t)row * DD + t];
    float s = v, sq = v * v;
    #pragma unroll
    for (int o = 16; o; o >>= 1) {
        s  += __shfl_down_sync(0xffffffffu, s,  o);
        sq += __shfl_down_sync(0xffffffffu, sq, o);
    }
    if ((t & 31) == 0) { sh[t >> 5] = s; sh[(t >> 5) + 8] = sq; }
    __syncthreads();
    if (t == 0) {
        float ts = 0.f, tq = 0.f;
        #pragma unroll
        for (int k = 0; k < 8; ++k) { ts += sh[k]; tq += sh[k + 8]; }
        float mu = ts * (1.0f / 256.0f);
        float var = tq * (1.0f / 256.0f) - mu * mu;
        stats[0] = mu; stats[1] = rsqrtf(var + 1e-5f);
    }
    __syncthreads();
    out[(size_t)row * DD + t] = (v - stats[0]) * stats[1] * gam[t] + bet[t];
}

// ---------------- fp32 64x32 GEMM tile for the small GEMMs ----------------
__device__ __forceinline__ void gemm_tile64x32(
    const float* __restrict__ A, const float* __restrict__ B,
    int lda, int ldb, int K, int m0, int n0, float acc[8]) {
    __shared__ __align__(16) float AsT[32][68];
    __shared__ float Bs[32][33];
    const int t = threadIdx.x, tn = t & 31, tg = t >> 5;
    #pragma unroll
    for (int q = 0; q < 8; ++q) acc[q] = 0.f;
    for (int k0 = 0; k0 < K; k0 += 32) {
        #pragma unroll
        for (int ph = 0; ph < 2; ++ph) {
            int flat = t + 256 * ph;
            int m = flat >> 3, kc = (flat & 7) << 2;
            float4 av = *(const float4*)(A + (size_t)(m0 + m) * lda + k0 + kc);
            AsT[kc + 0][m] = av.x; AsT[kc + 1][m] = av.y;
            AsT[kc + 2][m] = av.z; AsT[kc + 3][m] = av.w;
        }
        {
            int kr = t >> 3, nc = (t & 7) << 2;
            float4 bv = *(const float4*)(B + (size_t)(k0 + kr) * ldb + n0 + nc);
            Bs[kr][nc + 0] = bv.x; Bs[kr][nc + 1] = bv.y;
            Bs[kr][nc + 2] = bv.z; Bs[kr][nc + 3] = bv.w;
        }
        __syncthreads();
        #pragma unroll
        for (int kk = 0; kk < 32; ++kk) {
            float4 a0 = *(const float4*)&AsT[kk][tg * 8];
            float4 a1 = *(const float4*)&AsT[kk][tg * 8 + 4];
            float bb = Bs[kk][tn];
            acc[0] = fmaf(a0.x, bb, acc[0]); acc[1] = fmaf(a0.y, bb, acc[1]);
            acc[2] = fmaf(a0.z, bb, acc[2]); acc[3] = fmaf(a0.w, bb, acc[3]);
            acc[4] = fmaf(a1.x, bb, acc[4]); acc[5] = fmaf(a1.y, bb, acc[5]);
            acc[6] = fmaf(a1.z, bb, acc[6]); acc[7] = fmaf(a1.w, bb, acc[7]);
        }
        __syncthreads();
    }
}

__global__ __launch_bounds__(256) void gemm_bias(
    const float* __restrict__ A, const float* __restrict__ B,
    const float* __restrict__ bias, float* __restrict__ C,
    int lda, int ldb, int ldc, int K) {
    float acc[8];
    const int m0 = blockIdx.x * 64, n0 = blockIdx.y * 32;
    gemm_tile64x32(A, B, lda, ldb, K, m0, n0, acc);
    const int tn = threadIdx.x & 31, tg = threadIdx.x >> 5;
    const float bb = bias[n0 + tn];
    #pragma unroll
    for (int q = 0; q < 8; ++q)
        C[(size_t)(m0 + tg * 8 + q) * ldc + n0 + tn] = acc[q] + bb;
}

__global__ __launch_bounds__(256) void gemm_bias_res(
    const float* __restrict__ A, const float* __restrict__ B,
    const float* __restrict__ bias, const float* __restrict__ R,
    float* __restrict__ C, int lda, int ldb, int ldc, int K) {
    float acc[8];
    const int m0 = blockIdx.x * 64, n0 = blockIdx.y * 32;
    gemm_tile64x32(A, B, lda, ldb, K, m0, n0, acc);
    const int tn = threadIdx.x & 31, tg = threadIdx.x >> 5;
    const float bb = bias[n0 + tn];
    #pragma unroll
    for (int q = 0; q < 8; ++q) {
        size_t idx = (size_t)(m0 + tg * 8 + q) * ldc + n0 + tn;
        C[idx] = acc[q] + bb + R[idx];
    }
}

__global__ __launch_bounds__(256) void gemm_gelu(
    const float* __restrict__ A, const float* __restrict__ B,
    const float* __restrict__ bias, float* __restrict__ C,
    int lda, int ldb, int ldc, int K) {
    float acc[8];
    const int m0 = blockIdx.x * 64, n0 = blockIdx.y * 32;
    gemm_tile64x32(A, B, lda, ldb, K, m0, n0, acc);
    const int tn = threadIdx.x & 31, tg = threadIdx.x >> 5;
    const float bb = bias[n0 + tn];
    #pragma unroll
    for (int q = 0; q < 8; ++q) {
        float v = acc[q] + bb;
        C[(size_t)(m0 + tg * 8 + q) * ldc + n0 + tn] =
            0.5f * v * (1.0f + erff(v * 0.70710678118654752f));
    }
}

__global__ __launch_bounds__(256) void attnv_kernel(
    const float* __restrict__ scores, const float* __restrict__ nq,
    float* __restrict__ ao) {
    const int z = blockIdx.z, b = z >> 3, h = z & 7;
    const float* A = scores + (size_t)z * NN * NN;
    const float* B = nq + (size_t)b * NN * DD + h * 32;
    float acc[8];
    const int m0 = blockIdx.x * 64;
    gemm_tile64x32(A, B, NN, DD, NN, m0, 0, acc);
    const int tn = threadIdx.x & 31, tg = threadIdx.x >> 5;
    #pragma unroll
    for (int q = 0; q < 8; ++q)
        ao[((size_t)b * NN + (m0 + tg * 8 + q)) * DD + h * 32 + tn] = acc[q];
}

// ---------------- softmax (last dim 256, in place) ----------------
__global__ void softmax_kernel(float* __restrict__ sc) {
    __shared__ float sh[8];
    __shared__ float red;
    const size_t row = blockIdx.x;
    const int t = threadIdx.x;
    float v = sc[row * NN + t];
    float m = v;
    #pragma unroll
    for (int o = 16; o; o >>= 1) m = fmaxf(m, __shfl_xor_sync(0xffffffffu, m, o));
    if ((t & 31) == 0) sh[t >> 5] = m;
    __syncthreads();
    if (t == 0) {
        float mm = sh[0];
        #pragma unroll
        for (int w = 1; w < 8; ++w) mm = fmaxf(mm, sh[w]);
        red = mm;
    }
    __syncthreads();
    m = red;
    float e = expf(v - m);
    float s = e;
    #pragma unroll
    for (int o = 16; o; o >>= 1) s += __shfl_xor_sync(0xffffffffu, s, o);
    __syncthreads();
    if ((t & 31) == 0) sh[t >> 5] = s;
    __syncthreads();
    if (t == 0) {
        float ss = 0.f;
        #pragma unroll
        for (int w = 0; w < 8; ++w) ss += sh[w];
        red = 1.0f / ss;
    }
    __syncthreads();
    sc[row * NN + t] = e * red;
}

extern "C" void kernel_launch(void* const* d_in, const int* in_sizes, int n_in,
                              void* d_out, int out_size) {
    const float* nodes = (const float*)d_in[0];
    const float* edges = (const float*)d_in[1];
    const float* W     = (const float*)d_in[2];
    const float* b     = (const float*)d_in[3];
    const float* ln_g  = (const float*)d_in[4];
    const float* ln_b  = (const float*)d_in[5];
    const float* W1    = (const float*)d_in[6];
    const float* b1    = (const float*)d_in[7];
    const float* W2    = (const float*)d_in[8];
    const float* b2    = (const float*)d_in[9];
    float* out = (float*)d_out;

    float *px, *pnq, *psc, *pao, *pr, *px2, *phg;
    __half *pwh, *pwl;
    cudaGetSymbolAddress((void**)&px,  g_x);
    cudaGetSymbolAddress((void**)&pnq, g_nq);
    cudaGetSymbolAddress((void**)&psc, g_sc);
    cudaGetSymbolAddress((void**)&pao, g_ao);
    cudaGetSymbolAddress((void**)&pr,  g_r);
    cudaGetSymbolAddress((void**)&px2, g_x2);
    cudaGetSymbolAddress((void**)&phg, g_hg);
    cudaGetSymbolAddress((void**)&pwh, g_wh);
    cudaGetSymbolAddress((void**)&pwl, g_wl);

    cudaFuncSetAttribute(edge_mma_kernel,
                         cudaFuncAttributeMaxDynamicSharedMemorySize, EDGE_SMEM);

    prep_w<<<256, 256>>>(W, pwh, pwl);
    ln_kernel<<<NB * NN, 256>>>(nodes, ln_g, ln_b, px);
    gemm_bias<<<dim3(8, 8), 256>>>(px, W, b, pnq, DD, DD, DD, DD);
    edge_mma_kernel<<<dim3(2, NN, NB), 512, EDGE_SMEM>>>(edges, pwh, pwl, b, pnq, psc);
    softmax_kernel<<<NB * NH * NN, 256>>>(psc);
    attnv_kernel<<<dim3(4, 1, NB * NH), 256>>>(psc, pnq, pao);
    gemm_bias_res<<<dim3(8, 8), 256>>>(pao, W, b, px, pr, DD, DD, DD, DD);
    ln_kernel<<<NB * NN, 256>>>(pr, ln_g, ln_b, px2);
    gemm_gelu<<<dim3(8, 32), 256>>>(px2, W1, b1, phg, DD, FFD, FFD, DD);
    gemm_bias_res<<<dim3(8, 8), 256>>>(phg, W2, b2, px2, out, FFD, DD, DD, FFD);
}

// round 12
// speedup vs baseline: 1.1132x; 1.1132x over previous
#include <cuda_runtime.h>
#include <cuda_fp16.h>
#include <cuda_bf16.h>
#include <math.h>
#include <stdint.h>

#define NB 2
#define NN 256
#define DD 256
#define NH 8
#define FFD 1024

// ---------------- scratch (static device globals) ----------------
__device__ float g_x [NB*NN*DD];
__device__ float g_nq[NB*NN*DD];
__device__ float g_sc[(size_t)NB*NH*NN*NN];
__device__ float g_ao[NB*NN*DD];
__device__ float g_r [NB*NN*DD];
__device__ float g_x2[NB*NN*DD];
__device__ float g_hg[NB*NN*FFD];
__device__ __half g_wq[8*256*64];   // packed W units: 8 k32-chunks x 256 n x 8 units x 8 halves = 256 KB

// ---------------- helpers ----------------
__device__ __forceinline__ uint32_t smem_u32(const void* p) {
    uint32_t a;
    asm("{ .reg .u64 t; cvta.to.shared.u64 t, %1; cvt.u32.u64 %0, t; }" : "=r"(a) : "l"(p));
    return a;
}
#define CP16(dst, src) \
    asm volatile("cp.async.cg.shared.global [%0], [%1], 16;" :: "r"(dst), "l"(src))
#define CP_COMMIT() asm volatile("cp.async.commit_group;" ::: "memory")
#define CP_WAIT0() asm volatile("cp.async.wait_group 0;" ::: "memory")
#define CP_WAIT1() asm volatile("cp.async.wait_group 1;" ::: "memory")

__device__ __forceinline__ void mma16816(float* acc, const uint32_t* a,
                                         uint32_t b0, uint32_t b1) {
    asm volatile(
        "mma.sync.aligned.m16n8k16.row.col.f32.f16.f16.f32 "
        "{%0,%1,%2,%3}, {%4,%5,%6,%7}, {%8,%9}, {%0,%1,%2,%3};"
        : "+f"(acc[0]), "+f"(acc[1]), "+f"(acc[2]), "+f"(acc[3])
        : "r"(a[0]), "r"(a[1]), "r"(a[2]), "r"(a[3]), "r"(b0), "r"(b1));
}

__device__ __forceinline__ void split_f2(float2 v, uint32_t &hi, uint32_t &lo) {
    __half hx = __float2half_rn(v.x), hy = __float2half_rn(v.y);
    __half lx = __float2half_rn(v.x - __half2float(hx));
    __half ly = __float2half_rn(v.y - __half2float(hy));
    hi = (uint32_t)__half_as_ushort(hx) | ((uint32_t)__half_as_ushort(hy) << 16);
    lo = (uint32_t)__half_as_ushort(lx) | ((uint32_t)__half_as_ushort(ly) << 16);
}

// ---------------- prep W: 16B units for k32 chunks --------------------------
// id = c*2048 + n*8 + s*4 + p  (c:0..7 k32-chunk, n:0..255, s:0..1 k16, p:0..3)
// unit halves: hi(ka),hi(ka+1),hi(ka+8),hi(ka+9), lo(same); ka = c*32+s*16+p*2
__global__ void prep_w(const float* __restrict__ W, __half* __restrict__ wq) {
    int id = blockIdx.x * 256 + threadIdx.x;     // 16384
    int p = id & 3, s = (id >> 2) & 1, n = (id >> 3) & 255, c = id >> 11;
    int ka = c * 32 + s * 16 + p * 2;
    __half u[8];
    #pragma unroll
    for (int q = 0; q < 4; ++q) {
        int k = ka + (q >> 1) * 8 + (q & 1);
        float v = W[k * 256 + n];
        __half h = __float2half_rn(v);
        u[q] = h;
        u[q + 4] = __float2half_rn(v - __half2float(h));
    }
    *(uint4*)(wq + (size_t)id * 8) = *(uint4*)u;
}

// ---------------- fused edge GEMM (mma fp16x3), 2 CTAs/SM -------------------
// grid (x=4: jt|nh, i=256, b=2), 256 threads (8 warps).
// CTA: 128 rows (jt) x 128 cols (nh). Warp (wr=w&3, wc=w>>2): 32 rows x 64 cols.
#define A_PITCH 160
#define A_ST    (128*A_PITCH)     // 20480 per stage
#define B_OFF   (2*A_ST)          // 40960
#define B_ST    16384             // 128 n x 128B
#define MISC    (B_OFF + 2*B_ST)  // 73728
#define EDGE_SMEM (MISC + 2048)   // 75776

__global__ __launch_bounds__(256, 2) void edge_mma_kernel(
    const float* __restrict__ edges, const __half* __restrict__ wq,
    const float* __restrict__ bias, const float* __restrict__ nq,
    float* __restrict__ scores) {
    extern __shared__ char smem[];
    const uint32_t sb = smem_u32(smem);
    const int t = threadIdx.x, lane = t & 31, w = t >> 5;
    const int qp = lane & 3, lg = lane >> 2;
    const int wr = w & 3, wc = w >> 2;          // wc in {0,1}
    const int jt = blockIdx.x & 1, nh = blockIdx.x >> 1;
    const int i = blockIdx.y, b = blockIdx.z;
    const size_t r0 = ((size_t)(b * NN + i)) * NN + jt * 128;
    const char* eg = (const char*)(edges + r0 * DD);
    const char* wg = (const char*)wq;           // unit (c,n,u7) at ((c*256+n)*8+u7)*16

    // stage bias + nq_i
    float* sBias = (float*)(smem + MISC);
    float* sNqi  = sBias + 256;
    sBias[t] = bias[t];
    sNqi[t]  = nq[((size_t)(b * NN + i)) * DD + t];

    // prologue: chunks 0,1 -> stages 0,1
    #pragma unroll
    for (int c = 0; c < 2; ++c) {
        #pragma unroll
        for (int it = 0; it < 4; ++it) {        // A: 1024 units
            int u = t + 256 * it, row = u >> 3, part = u & 7;
            CP16(sb + c * A_ST + row * A_PITCH + part * 16,
                 eg + (size_t)row * 1024 + c * 128 + part * 16);
        }
        #pragma unroll
        for (int it = 0; it < 4; ++it) {        // B: 1024 units
            int u = t + 256 * it, n = u >> 3, u7 = u & 7;
            int us = u7 ^ ((n & 1) << 2);
            CP16(sb + B_OFF + c * B_ST + n * 128 + us * 16,
                 wg + ((size_t)(c * 256 + nh * 128 + n) * 8 + u7) * 16);
        }
        CP_COMMIT();
    }

    float acc[64];                              // [m(2)][nt(8)][4]
    #pragma unroll
    for (int q = 0; q < 64; ++q) acc[q] = 0.f;

    const int rbase = wr * 32 + lg;

    #pragma unroll 1
    for (int c = 0; c < 8; ++c) {
        if (c < 7) { CP_WAIT1(); } else { CP_WAIT0(); }
        __syncthreads();
        const int st = c & 1;
        const char* abase = smem + st * A_ST;
        const char* bbase = smem + B_OFF + st * B_ST;

        #pragma unroll
        for (int s = 0; s < 2; ++s) {
            uint32_t AH[2][4], AL[2][4];
            #pragma unroll
            for (int m = 0; m < 2; ++m) {
                const char* ar = abase + (rbase + m * 16) * A_PITCH + s * 64 + qp * 8;
                float2 va = *(const float2*)(ar);
                float2 vb = *(const float2*)(ar + 8 * A_PITCH);
                float2 vc = *(const float2*)(ar + 32);
                float2 vd = *(const float2*)(ar + 8 * A_PITCH + 32);
                split_f2(va, AH[m][0], AL[m][0]);
                split_f2(vb, AH[m][1], AL[m][1]);
                split_f2(vc, AH[m][2], AL[m][2]);
                split_f2(vd, AH[m][3], AL[m][3]);
            }
            #pragma unroll
            for (int nt = 0; nt < 8; ++nt) {
                const int n = wc * 64 + nt * 8 + lg;            // 0..127
                const int ur = (s * 4 + qp) ^ ((n & 1) << 2);
                uint4 v = *(const uint4*)(bbase + n * 128 + ur * 16);
                #pragma unroll
                for (int m = 0; m < 2; ++m) {
                    float* ac = &acc[(m * 8 + nt) * 4];
                    mma16816(ac, AH[m], v.x, v.y);
                    mma16816(ac, AH[m], v.z, v.w);
                    mma16816(ac, AL[m], v.x, v.y);
                }
            }
        }
        __syncthreads();
        if (c < 6) {                            // chunk c+2 -> stage st
            const int cn = c + 2;
            #pragma unroll
            for (int it = 0; it < 4; ++it) {
                int u = t + 256 * it, row = u >> 3, part = u & 7;
                CP16(sb + st * A_ST + row * A_PITCH + part * 16,
                     eg + (size_t)row * 1024 + cn * 128 + part * 16);
            }
            #pragma unroll
            for (int it = 0; it < 4; ++it) {
                int u = t + 256 * it, n = u >> 3, u7 = u & 7;
                int us = u7 ^ ((n & 1) << 2);
                CP16(sb + B_OFF + st * B_ST + n * 128 + us * 16,
                     wg + ((size_t)(cn * 256 + nh * 128 + n) * 8 + u7) * 16);
            }
            CP_COMMIT();
        }
    }

    // ---- epilogue: per-head score reduction (this CTA covers 4 heads) ----
    const float* nqb = nq + ((size_t)b * NN) * DD;
    const float invs = 0.17677669529663687f;   // 1/sqrt(32)
    #pragma unroll
    for (int m = 0; m < 2; ++m) {
        const int jb = jt * 128 + wr * 32 + m * 16 + lg;
        #pragma unroll
        for (int hh = 0; hh < 2; ++hh) {
            const int h = nh * 4 + wc * 2 + hh;
            float s1 = 0.f, s2 = 0.f;
            #pragma unroll
            for (int k = 0; k < 4; ++k) {
                const int nt = hh * 4 + k;
                const int col = nh * 128 + wc * 64 + nt * 8 + qp * 2;
                const float* a = &acc[(m * 8 + nt) * 4];
                float2 q1 = *(const float2*)(nqb + (size_t)jb * DD + col);
                float2 q2 = *(const float2*)(nqb + (size_t)(jb + 8) * DD + col);
                float bi0 = sBias[col], bi1 = sBias[col + 1];
                float ni0 = sNqi[col],  ni1 = sNqi[col + 1];
                float e;
                e = a[0] + bi0; s1 += (e + ni0) * (e + q1.x);
                e = a[1] + bi1; s1 += (e + ni1) * (e + q1.y);
                e = a[2] + bi0; s2 += (e + ni0) * (e + q2.x);
                e = a[3] + bi1; s2 += (e + ni1) * (e + q2.y);
            }
            s1 += __shfl_xor_sync(0xffffffffu, s1, 1);
            s1 += __shfl_xor_sync(0xffffffffu, s1, 2);
            s2 += __shfl_xor_sync(0xffffffffu, s2, 1);
            s2 += __shfl_xor_sync(0xffffffffu, s2, 2);
            if (qp == 0) {
                float* sp = scores + (((size_t)(b * NH + h)) << 16) + (size_t)i * NN;
                sp[jb]     = 10.0f * tanhf(s1 * invs);
                sp[jb + 8] = 10.0f * tanhf(s2 * invs);
            }
        }
    }
}

// ---------------- LayerNorm ----------------
__global__ void ln_kernel(const float* __restrict__ in,
                          const float* __restrict__ gam,
                          const float* __restrict__ bet,
                          float* __restrict__ out) {
    __shared__ float sh[16];
    __shared__ float stats[2];
    const int row = blockIdx.x, t = threadIdx.x;
    float v = in[(size_t)row * DD + t];
    float s = v, sq = v * v;
    #pragma unroll
    for (int o = 16; o; o >>= 1) {
        s  += __shfl_down_sync(0xffffffffu, s,  o);
        sq += __shfl_down_sync(0xffffffffu, sq, o);
    }
    if ((t & 31) == 0) { sh[t >> 5] = s; sh[(t >> 5) + 8] = sq; }
    __syncthreads();
    if (t == 0) {
        float ts = 0.f, tq = 0.f;
        #pragma unroll
        for (int k = 0; k < 8; ++k) { ts += sh[k]; tq += sh[k + 8]; }
        float mu = ts * (1.0f / 256.0f);
        float var = tq * (1.0f / 256.0f) - mu * mu;
        stats[0] = mu; stats[1] = rsqrtf(var + 1e-5f);
    }
    __syncthreads();
    out[(size_t)row * DD + t] = (v - stats[0]) * stats[1] * gam[t] + bet[t];
}

// ---------------- fp32 64x32 GEMM tile for the small GEMMs ----------------
__device__ __forceinline__ void gemm_tile64x32(
    const float* __restrict__ A, const float* __restrict__ B,
    int lda, int ldb, int K, int m0, int n0, float acc[8]) {
    __shared__ __align__(16) float AsT[32][68];
    __shared__ float Bs[32][33];
    const int t = threadIdx.x, tn = t & 31, tg = t >> 5;
    #pragma unroll
    for (int q = 0; q < 8; ++q) acc[q] = 0.f;
    for (int k0 = 0; k0 < K; k0 += 32) {
        #pragma unroll
        for (int ph = 0; ph < 2; ++ph) {
            int flat = t + 256 * ph;
            int m = flat >> 3, kc = (flat & 7) << 2;
            float4 av = *(const float4*)(A + (size_t)(m0 + m) * lda + k0 + kc);
            AsT[kc + 0][m] = av.x; AsT[kc + 1][m] = av.y;
            AsT[kc + 2][m] = av.z; AsT[kc + 3][m] = av.w;
        }
        {
            int kr = t >> 3, nc = (t & 7) << 2;
            float4 bv = *(const float4*)(B + (size_t)(k0 + kr) * ldb + n0 + nc);
            Bs[kr][nc + 0] = bv.x; Bs[kr][nc + 1] = bv.y;
            Bs[kr][nc + 2] = bv.z; Bs[kr][nc + 3] = bv.w;
        }
        __syncthreads();
        #pragma unroll
        for (int kk = 0; kk < 32; ++kk) {
            float4 a0 = *(const float4*)&AsT[kk][tg * 8];
            float4 a1 = *(const float4*)&AsT[kk][tg * 8 + 4];
            float bb = Bs[kk][tn];
            acc[0] = fmaf(a0.x, bb, acc[0]); acc[1] = fmaf(a0.y, bb, acc[1]);
            acc[2] = fmaf(a0.z, bb, acc[2]); acc[3] = fmaf(a0.w, bb, acc[3]);
            acc[4] = fmaf(a1.x, bb, acc[4]); acc[5] = fmaf(a1.y, bb, acc[5]);
            acc[6] = fmaf(a1.z, bb, acc[6]); acc[7] = fmaf(a1.w, bb, acc[7]);
        }
        __syncthreads();
    }
}

__global__ __launch_bounds__(256) void gemm_bias(
    const float* __restrict__ A, const float* __restrict__ B,
    const float* __restrict__ bias, float* __restrict__ C,
    int lda, int ldb, int ldc, int K) {
    float acc[8];
    const int m0 = blockIdx.x * 64, n0 = blockIdx.y * 32;
    gemm_tile64x32(A, B, lda, ldb, K, m0, n0, acc);
    const int tn = threadIdx.x & 31, tg = threadIdx.x >> 5;
    const float bb = bias[n0 + tn];
    #pragma unroll
    for (int q = 0; q < 8; ++q)
        C[(size_t)(m0 + tg * 8 + q) * ldc + n0 + tn] = acc[q] + bb;
}

__global__ __launch_bounds__(256) void gemm_bias_res(
    const float* __restrict__ A, const float* __restrict__ B,
    const float* __restrict__ bias, const float* __restrict__ R,
    float* __restrict__ C, int lda, int ldb, int ldc, int K) {
    float acc[8];
    const int m0 = blockIdx.x * 64, n0 = blockIdx.y * 32;
    gemm_tile64x32(A, B, lda, ldb, K, m0, n0, acc);
    const int tn = threadIdx.x & 31, tg = threadIdx.x >> 5;
    const float bb = bias[n0 + tn];
    #pragma unroll
    for (int q = 0; q < 8; ++q) {
        size_t idx = (size_t)(m0 + tg * 8 + q) * ldc + n0 + tn;
        C[idx] = acc[q] + bb + R[idx];
    }
}

__global__ __launch_bounds__(256) void gemm_gelu(
    const float* __restrict__ A, const float* __restrict__ B,
    const float* __restrict__ bias, float* __restrict__ C,
    int lda, int ldb, int ldc, int K) {
    float acc[8];
    const int m0 = blockIdx.x * 64, n0 = blockIdx.y * 32;
    gemm_tile64x32(A, B, lda, ldb, K, m0, n0, acc);
    const int tn = threadIdx.x & 31, tg = threadIdx.x >> 5;
    const float bb = bias[n0 + tn];
    #pragma unroll
    for (int q = 0; q < 8; ++q) {
        float v = acc[q] + bb;
        C[(size_t)(m0 + tg * 8 + q) * ldc + n0 + tn] =
            0.5f * v * (1.0f + erff(v * 0.70710678118654752f));
    }
}

__global__ __launch_bounds__(256) void attnv_kernel(
    const float* __restrict__ scores, const float* __restrict__ nq,
    float* __restrict__ ao) {
    const int z = blockIdx.z, b = z >> 3, h = z & 7;
    const float* A = scores + (size_t)z * NN * NN;
    const float* B = nq + (size_t)b * NN * DD + h * 32;
    float acc[8];
    const int m0 = blockIdx.x * 64;
    gemm_tile64x32(A, B, NN, DD, NN, m0, 0, acc);
    const int tn = threadIdx.x & 31, tg = threadIdx.x >> 5;
    #pragma unroll
    for (int q = 0; q < 8; ++q)
        ao[((size_t)b * NN + (m0 + tg * 8 + q)) * DD + h * 32 + tn] = acc[q];
}

// ---------------- softmax (last dim 256, in place) ----------------
__global__ void softmax_kernel(float* __restrict__ sc) {
    __shared__ float sh[8];
    __shared__ float red;
    const size_t row = blockIdx.x;
    const int t = threadIdx.x;
    float v = sc[row * NN + t];
    float m = v;
    #pragma unroll
    for (int o = 16; o; o >>= 1) m = fmaxf(m, __shfl_xor_sync(0xffffffffu, m, o));
    if ((t & 31) == 0) sh[t >> 5] = m;
    __syncthreads();
    if (t == 0) {
        float mm = sh[0];
        #pragma unroll
        for (int w = 1; w < 8; ++w) mm = fmaxf(mm, sh[w]);
        red = mm;
    }
    __syncthreads();
    m = red;
    float e = expf(v - m);
    float s = e;
    #pragma unroll
    for (int o = 16; o; o >>= 1) s += __shfl_xor_sync(0xffffffffu, s, o);
    __syncthreads();
    if ((t & 31) == 0) sh[t >> 5] = s;
    __syncthreads();
    if (t == 0) {
        float ss = 0.f;
        #pragma unroll
        for (int w = 0; w < 8; ++w) ss += sh[w];
        red = 1.0f / ss;
    }
    __syncthreads();
    sc[row * NN + t] = e * red;
}

extern "C" void kernel_launch(void* const* d_in, const int* in_sizes, int n_in,
                              void* d_out, int out_size) {
    const float* nodes = (const float*)d_in[0];
    const float* edges = (const float*)d_in[1];
    const float* W     = (const float*)d_in[2];
    const float* b     = (const float*)d_in[3];
    const float* ln_g  = (const float*)d_in[4];
    const float* ln_b  = (const float*)d_in[5];
    const float* W1    = (const float*)d_in[6];
    const float* b1    = (const float*)d_in[7];
    const float* W2    = (const float*)d_in[8];
    const float* b2    = (const float*)d_in[9];
    float* out = (float*)d_out;

    float *px, *pnq, *psc, *pao, *pr, *px2, *phg;
    __half *pwq;
    cudaGetSymbolAddress((void**)&px,  g_x);
    cudaGetSymbolAddress((void**)&pnq, g_nq);
    cudaGetSymbolAddress((void**)&psc, g_sc);
    cudaGetSymbolAddress((void**)&pao, g_ao);
    cudaGetSymbolAddress((void**)&pr,  g_r);
    cudaGetSymbolAddress((void**)&px2, g_x2);
    cudaGetSymbolAddress((void**)&phg, g_hg);
    cudaGetSymbolAddress((void**)&pwq, g_wq);

    cudaFuncSetAttribute(edge_mma_kernel,
                         cudaFuncAttributeMaxDynamicSharedMemorySize, EDGE_SMEM);

    prep_w<<<64, 256>>>(W, pwq);
    ln_kernel<<<NB * NN, 256>>>(nodes, ln_g, ln_b, px);
    gemm_bias<<<dim3(8, 8), 256>>>(px, W, b, pnq, DD, DD, DD, DD);
    edge_mma_kernel<<<dim3(4, NN, NB), 256, EDGE_SMEM>>>(edges, pwq, b, pnq, psc);
    softmax_kernel<<<NB * NH * NN, 256>>>(psc);
    attnv_kernel<<<dim3(4, 1, NB * NH), 256>>>(psc, pnq, pao);
    gemm_bias_res<<<dim3(8, 8), 256>>>(pao, W, b, px, pr, DD, DD, DD, DD);
    ln_kernel<<<NB * NN, 256>>>(pr, ln_g, ln_b, px2);
    gemm_gelu<<<dim3(8, 32), 256>>>(px2, W1, b1, phg, DD, FFD, FFD, DD);
    gemm_bias_res<<<dim3(8, 8), 256>>>(phg, W2, b2, px2, out, FFD, DD, DD, FFD);
}

// round 13
// speedup vs baseline: 1.1704x; 1.0514x over previous
#include <cuda_runtime.h>
#include <cuda_fp16.h>
#include <cuda_bf16.h>
#include <math.h>
#include <stdint.h>

#define NB 2
#define NN 256
#define DD 256
#define NH 8
#define FFD 1024

// ---------------- scratch (static device globals) ----------------
__device__ float g_x [NB*NN*DD];
__device__ float g_nq[NB*NN*DD];
__device__ float g_sc[(size_t)NB*NH*NN*NN];
__device__ float g_ao[NB*NN*DD];
__device__ float g_r [NB*NN*DD];
__device__ float g_x2[NB*NN*DD];
__device__ float g_hg[NB*NN*FFD];
__device__ __half g_wq[8*256*64];   // packed W units: 8 k32-chunks x 256 n x 8 units x 8 halves

// ---------------- helpers ----------------
__device__ __forceinline__ uint32_t smem_u32(const void* p) {
    uint32_t a;
    asm("{ .reg .u64 t; cvta.to.shared.u64 t, %1; cvt.u32.u64 %0, t; }" : "=r"(a) : "l"(p));
    return a;
}
#define CP16(dst, src) \
    asm volatile("cp.async.cg.shared.global [%0], [%1], 16;" :: "r"(dst), "l"(src))
#define CP_COMMIT() asm volatile("cp.async.commit_group;" ::: "memory")
#define CP_WAIT0() asm volatile("cp.async.wait_group 0;" ::: "memory")
#define CP_WAIT1() asm volatile("cp.async.wait_group 1;" ::: "memory")

__device__ __forceinline__ void mma16816(float* acc, const uint32_t* a,
                                         uint32_t b0, uint32_t b1) {
    asm volatile(
        "mma.sync.aligned.m16n8k16.row.col.f32.f16.f16.f32 "
        "{%0,%1,%2,%3}, {%4,%5,%6,%7}, {%8,%9}, {%0,%1,%2,%3};"
        : "+f"(acc[0]), "+f"(acc[1]), "+f"(acc[2]), "+f"(acc[3])
        : "r"(a[0]), "r"(a[1]), "r"(a[2]), "r"(a[3]), "r"(b0), "r"(b1));
}

__device__ __forceinline__ void split_f2(float2 v, uint32_t &hi, uint32_t &lo) {
    __half hx = __float2half_rn(v.x), hy = __float2half_rn(v.y);
    __half lx = __float2half_rn(v.x - __half2float(hx));
    __half ly = __float2half_rn(v.y - __half2float(hy));
    hi = (uint32_t)__half_as_ushort(hx) | ((uint32_t)__half_as_ushort(hy) << 16);
    lo = (uint32_t)__half_as_ushort(lx) | ((uint32_t)__half_as_ushort(ly) << 16);
}

// f32x2 packed helpers (for fp32 small GEMMs)
__device__ __forceinline__ unsigned long long dup2(float x) {
    unsigned long long r;
    asm("mov.b64 %0, {%1, %1};" : "=l"(r) : "f"(x));
    return r;
}
__device__ __forceinline__ void fma2(unsigned long long &d,
                                     unsigned long long a, unsigned long long b) {
    asm("fma.rn.f32x2 %0, %1, %2, %0;" : "+l"(d) : "l"(a), "l"(b));
}
__device__ __forceinline__ void unpack2(unsigned long long v, float &lo, float &hi) {
    asm("mov.b64 {%0, %1}, %2;" : "=f"(lo), "=f"(hi) : "l"(v));
}

// ---------------- prep W: 16B units for k32 chunks --------------------------
// id = c*2048 + n*8 + s*4 + p; unit: hi(ka),hi(ka+1),hi(ka+8),hi(ka+9), lo same
__global__ void prep_w(const float* __restrict__ W, __half* __restrict__ wq) {
    int id = blockIdx.x * 256 + threadIdx.x;     // 16384
    int p = id & 3, s = (id >> 2) & 1, n = (id >> 3) & 255, c = id >> 11;
    int ka = c * 32 + s * 16 + p * 2;
    __half u[8];
    #pragma unroll
    for (int q = 0; q < 4; ++q) {
        int k = ka + (q >> 1) * 8 + (q & 1);
        float v = W[k * 256 + n];
        __half h = __float2half_rn(v);
        u[q] = h;
        u[q + 4] = __float2half_rn(v - __half2float(h));
    }
    *(uint4*)(wq + (size_t)id * 8) = *(uint4*)u;
}

// ---------------- fused edge GEMM (mma fp16x3), 4 CTAs/SM -------------------
// grid (x=8: jt(4)|nh(2), i=256, b=2), 128 threads (4 warps).
// CTA: 64 rows x 128 cols. Warp (wr=w&1, wc=w>>1): 32 rows x 64 cols.
#define A_PITCH 160
#define A_ST    (64*A_PITCH)      // 10240 per stage
#define B_OFF   (2*A_ST)          // 20480
#define B_ST    16384             // 128 n x 128B
#define MISC    (B_OFF + 2*B_ST)  // 53248
#define EDGE_SMEM (MISC + 1024)   // 54272

__global__ __launch_bounds__(128, 4) void edge_mma_kernel(
    const float* __restrict__ edges, const __half* __restrict__ wq,
    const float* __restrict__ bias, const float* __restrict__ nq,
    float* __restrict__ scores) {
    extern __shared__ char smem[];
    const uint32_t sb = smem_u32(smem);
    const int t = threadIdx.x, lane = t & 31, w = t >> 5;
    const int qp = lane & 3, lg = lane >> 2;
    const int wr = w & 1, wc = w >> 1;          // wr in {0,1}, wc in {0,1}
    const int jt = blockIdx.x & 3, nh = blockIdx.x >> 2;
    const int i = blockIdx.y, b = blockIdx.z;
    const size_t r0 = ((size_t)(b * NN + i)) * NN + jt * 64;
    const char* eg = (const char*)(edges + r0 * DD);
    const char* wg = (const char*)wq;           // unit (c,nglob,u7) at ((c*256+n)*8+u7)*16

    // stage local bias + nq_i (this CTA's 128 cols)
    float* sBias = (float*)(smem + MISC);       // [128]
    float* sNqi  = sBias + 128;                 // [128]
    sBias[t] = bias[nh * 128 + t];
    sNqi[t]  = nq[((size_t)(b * NN + i)) * DD + nh * 128 + t];

    // prologue: chunks 0,1 -> stages 0,1
    #pragma unroll
    for (int c = 0; c < 2; ++c) {
        #pragma unroll
        for (int it = 0; it < 4; ++it) {        // A: 512 units
            int u = t + 128 * it, row = u >> 3, part = u & 7;
            CP16(sb + c * A_ST + row * A_PITCH + part * 16,
                 eg + (size_t)row * 1024 + c * 128 + part * 16);
        }
        #pragma unroll
        for (int it = 0; it < 8; ++it) {        // B: 1024 units
            int u = t + 128 * it, n = u >> 3, u7 = u & 7;
            int us = u7 ^ ((n & 1) << 2);
            CP16(sb + B_OFF + c * B_ST + n * 128 + us * 16,
                 wg + ((size_t)(c * 256 + nh * 128 + n) * 8 + u7) * 16);
        }
        CP_COMMIT();
    }

    float acc[64];                              // [m(2)][nt(8)][4]
    #pragma unroll
    for (int q = 0; q < 64; ++q) acc[q] = 0.f;

    const int rbase = wr * 32 + lg;

    #pragma unroll 1
    for (int c = 0; c < 8; ++c) {
        if (c < 7) { CP_WAIT1(); } else { CP_WAIT0(); }
        __syncthreads();
        const int st = c & 1;
        const char* abase = smem + st * A_ST;
        const char* bbase = smem + B_OFF + st * B_ST;

        #pragma unroll
        for (int s = 0; s < 2; ++s) {
            uint32_t AH[2][4], AL[2][4];
            #pragma unroll
            for (int m = 0; m < 2; ++m) {
                const char* ar = abase + (rbase + m * 16) * A_PITCH + s * 64 + qp * 8;
                float2 va = *(const float2*)(ar);
                float2 vb = *(const float2*)(ar + 8 * A_PITCH);
                float2 vc = *(const float2*)(ar + 32);
                float2 vd = *(const float2*)(ar + 8 * A_PITCH + 32);
                split_f2(va, AH[m][0], AL[m][0]);
                split_f2(vb, AH[m][1], AL[m][1]);
                split_f2(vc, AH[m][2], AL[m][2]);
                split_f2(vd, AH[m][3], AL[m][3]);
            }
            #pragma unroll
            for (int nt = 0; nt < 8; ++nt) {
                const int n = wc * 64 + nt * 8 + lg;            // local 0..127
                const int ur = (s * 4 + qp) ^ ((n & 1) << 2);
                uint4 v = *(const uint4*)(bbase + n * 128 + ur * 16);
                #pragma unroll
                for (int m = 0; m < 2; ++m) {
                    float* ac = &acc[(m * 8 + nt) * 4];
                    mma16816(ac, AH[m], v.x, v.y);
                    mma16816(ac, AH[m], v.z, v.w);
                    mma16816(ac, AL[m], v.x, v.y);
                }
            }
        }
        __syncthreads();
        if (c < 6) {                            // chunk c+2 -> stage st
            const int cn = c + 2;
            #pragma unroll
            for (int it = 0; it < 4; ++it) {
                int u = t + 128 * it, row = u >> 3, part = u & 7;
                CP16(sb + st * A_ST + row * A_PITCH + part * 16,
                     eg + (size_t)row * 1024 + cn * 128 + part * 16);
            }
            #pragma unroll
            for (int it = 0; it < 8; ++it) {
                int u = t + 128 * it, n = u >> 3, u7 = u & 7;
                int us = u7 ^ ((n & 1) << 2);
                CP16(sb + B_OFF + st * B_ST + n * 128 + us * 16,
                     wg + ((size_t)(cn * 256 + nh * 128 + n) * 8 + u7) * 16);
            }
            CP_COMMIT();
        }
    }

    // ---- epilogue: per-head score reduction (CTA covers heads nh*4..nh*4+3) ----
    const float* nqb = nq + ((size_t)b * NN) * DD;
    const float invs = 0.17677669529663687f;   // 1/sqrt(32)
    #pragma unroll
    for (int m = 0; m < 2; ++m) {
        const int jb = jt * 64 + wr * 32 + m * 16 + lg;
        #pragma unroll
        for (int hh = 0; hh < 2; ++hh) {
            const int h = nh * 4 + wc * 2 + hh;
            float s1 = 0.f, s2 = 0.f;
            #pragma unroll
            for (int k = 0; k < 4; ++k) {
                const int nt = hh * 4 + k;
                const int cl = wc * 64 + nt * 8 + qp * 2;     // local col
                const int cg = nh * 128 + cl;                 // global col
                const float* a = &acc[(m * 8 + nt) * 4];
                float2 q1 = *(const float2*)(nqb + (size_t)jb * DD + cg);
                float2 q2 = *(const float2*)(nqb + (size_t)(jb + 8) * DD + cg);
                float bi0 = sBias[cl], bi1 = sBias[cl + 1];
                float ni0 = sNqi[cl],  ni1 = sNqi[cl + 1];
                float e;
                e = a[0] + bi0; s1 += (e + ni0) * (e + q1.x);
                e = a[1] + bi1; s1 += (e + ni1) * (e + q1.y);
                e = a[2] + bi0; s2 += (e + ni0) * (e + q2.x);
                e = a[3] + bi1; s2 += (e + ni1) * (e + q2.y);
            }
            s1 += __shfl_xor_sync(0xffffffffu, s1, 1);
            s1 += __shfl_xor_sync(0xffffffffu, s1, 2);
            s2 += __shfl_xor_sync(0xffffffffu, s2, 1);
            s2 += __shfl_xor_sync(0xffffffffu, s2, 2);
            if (qp == 0) {
                float* sp = scores + (((size_t)(b * NH + h)) << 16) + (size_t)i * NN;
                sp[jb]     = 10.0f * tanhf(s1 * invs);
                sp[jb + 8] = 10.0f * tanhf(s2 * invs);
            }
        }
    }
}

// ---------------- LayerNorm ----------------
__global__ void ln_kernel(const float* __restrict__ in,
                          const float* __restrict__ gam,
                          const float* __restrict__ bet,
                          float* __restrict__ out) {
    __shared__ float sh[16];
    __shared__ float stats[2];
    const int row = blockIdx.x, t = threadIdx.x;
    float v = in[(size_t)row * DD + t];
    float s = v, sq = v * v;
    #pragma unroll
    for (int o = 16; o; o >>= 1) {
        s  += __shfl_down_sync(0xffffffffu, s,  o);
        sq += __shfl_down_sync(0xffffffffu, sq, o);
    }
    if ((t & 31) == 0) { sh[t >> 5] = s; sh[(t >> 5) + 8] = sq; }
    __syncthreads();
    if (t == 0) {
        float ts = 0.f, tq = 0.f;
        #pragma unroll
        for (int k = 0; k < 8; ++k) { ts += sh[k]; tq += sh[k + 8]; }
        float mu = ts * (1.0f / 256.0f);
        float var = tq * (1.0f / 256.0f) - mu * mu;
        stats[0] = mu; stats[1] = rsqrtf(var + 1e-5f);
    }
    __syncthreads();
    out[(size_t)row * DD + t] = (v - stats[0]) * stats[1] * gam[t] + bet[t];
}

// ---------------- fp32 64x32 GEMM tile (f32x2 FMA) --------------------------
__device__ __forceinline__ void gemm_tile64x32(
    const float* __restrict__ A, const float* __restrict__ B,
    int lda, int ldb, int K, int m0, int n0, float acc[8]) {
    __shared__ __align__(16) float AsT[32][68];
    __shared__ float Bs[32][33];
    const int t = threadIdx.x, tn = t & 31, tg = t >> 5;
    unsigned long long acc2[4] = {0ull, 0ull, 0ull, 0ull};
    for (int k0 = 0; k0 < K; k0 += 32) {
        #pragma unroll
        for (int ph = 0; ph < 2; ++ph) {
            int flat = t + 256 * ph;
            int m = flat >> 3, kc = (flat & 7) << 2;
            float4 av = *(const float4*)(A + (size_t)(m0 + m) * lda + k0 + kc);
            AsT[kc + 0][m] = av.x; AsT[kc + 1][m] = av.y;
            AsT[kc + 2][m] = av.z; AsT[kc + 3][m] = av.w;
        }
        {
            int kr = t >> 3, nc = (t & 7) << 2;
            float4 bv = *(const float4*)(B + (size_t)(k0 + kr) * ldb + n0 + nc);
            Bs[kr][nc + 0] = bv.x; Bs[kr][nc + 1] = bv.y;
            Bs[kr][nc + 2] = bv.z; Bs[kr][nc + 3] = bv.w;
        }
        __syncthreads();
        #pragma unroll
        for (int kk = 0; kk < 32; ++kk) {
            ulonglong2 a01 = *(const ulonglong2*)&AsT[kk][tg * 8];
            ulonglong2 a23 = *(const ulonglong2*)&AsT[kk][tg * 8 + 4];
            unsigned long long b2 = dup2(Bs[kk][tn]);
            fma2(acc2[0], a01.x, b2);
            fma2(acc2[1], a01.y, b2);
            fma2(acc2[2], a23.x, b2);
            fma2(acc2[3], a23.y, b2);
        }
        __syncthreads();
    }
    unpack2(acc2[0], acc[0], acc[1]);
    unpack2(acc2[1], acc[2], acc[3]);
    unpack2(acc2[2], acc[4], acc[5]);
    unpack2(acc2[3], acc[6], acc[7]);
}

__global__ __launch_bounds__(256) void gemm_bias(
    const float* __restrict__ A, const float* __restrict__ B,
    const float* __restrict__ bias, float* __restrict__ C,
    int lda, int ldb, int ldc, int K) {
    float acc[8];
    const int m0 = blockIdx.x * 64, n0 = blockIdx.y * 32;
    gemm_tile64x32(A, B, lda, ldb, K, m0, n0, acc);
    const int tn = threadIdx.x & 31, tg = threadIdx.x >> 5;
    const float bb = bias[n0 + tn];
    #pragma unroll
    for (int q = 0; q < 8; ++q)
        C[(size_t)(m0 + tg * 8 + q) * ldc + n0 + tn] = acc[q] + bb;
}

__global__ __launch_bounds__(256) void gemm_bias_res(
    const float* __restrict__ A, const float* __restrict__ B,
    const float* __restrict__ bias, const float* __restrict__ R,
    float* __restrict__ C, int lda, int ldb, int ldc, int K) {
    float acc[8];
    const int m0 = blockIdx.x * 64, n0 = blockIdx.y * 32;
    gemm_tile64x32(A, B, lda, ldb, K, m0, n0, acc);
    const int tn = threadIdx.x & 31, tg = threadIdx.x >> 5;
    const float bb = bias[n0 + tn];
    #pragma unroll
    for (int q = 0; q < 8; ++q) {
        size_t idx = (size_t)(m0 + tg * 8 + q) * ldc + n0 + tn;
        C[idx] = acc[q] + bb + R[idx];
    }
}

__global__ __launch_bounds__(256) void gemm_gelu(
    const float* __restrict__ A, const float* __restrict__ B,
    const float* __restrict__ bias, float* __restrict__ C,
    int lda, int ldb, int ldc, int K) {
    float acc[8];
    const int m0 = blockIdx.x * 64, n0 = blockIdx.y * 32;
    gemm_tile64x32(A, B, lda, ldb, K, m0, n0, acc);
    const int tn = threadIdx.x & 31, tg = threadIdx.x >> 5;
    const float bb = bias[n0 + tn];
    #pragma unroll
    for (int q = 0; q < 8; ++q) {
        float v = acc[q] + bb;
        C[(size_t)(m0 + tg * 8 + q) * ldc + n0 + tn] =
            0.5f * v * (1.0f + erff(v * 0.70710678118654752f));
    }
}

__global__ __launch_bounds__(256) void attnv_kernel(
    const float* __restrict__ scores, const float* __restrict__ nq,
    float* __restrict__ ao) {
    const int z = blockIdx.z, b = z >> 3, h = z & 7;
    const float* A = scores + (size_t)z * NN * NN;
    const float* B = nq + (size_t)b * NN * DD + h * 32;
    float acc[8];
    const int m0 = blockIdx.x * 64;
    gemm_tile64x32(A, B, NN, DD, NN, m0, 0, acc);
    const int tn = threadIdx.x & 31, tg = threadIdx.x >> 5;
    #pragma unroll
    for (int q = 0; q < 8; ++q)
        ao[((size_t)b * NN + (m0 + tg * 8 + q)) * DD + h * 32 + tn] = acc[q];
}

// ---------------- softmax (last dim 256, in place) ----------------
__global__ void softmax_kernel(float* __restrict__ sc) {
    __shared__ float sh[8];
    __shared__ float red;
    const size_t row = blockIdx.x;
    const int t = threadIdx.x;
    float v = sc[row * NN + t];
    float m = v;
    #pragma unroll
    for (int o = 16; o; o >>= 1) m = fmaxf(m, __shfl_xor_sync(0xffffffffu, m, o));
    if ((t & 31) == 0) sh[t >> 5] = m;
    __syncthreads();
    if (t == 0) {
        float mm = sh[0];
        #pragma unroll
        for (int w = 1; w < 8; ++w) mm = fmaxf(mm, sh[w]);
        red = mm;
    }
    __syncthreads();
    m = red;
    float e = expf(v - m);
    float s = e;
    #pragma unroll
    for (int o = 16; o; o >>= 1) s += __shfl_xor_sync(0xffffffffu, s, o);
    __syncthreads();
    if ((t & 31) == 0) sh[t >> 5] = s;
    __syncthreads();
    if (t == 0) {
        float ss = 0.f;
        #pragma unroll
        for (int w = 0; w < 8; ++w) ss += sh[w];
        red = 1.0f / ss;
    }
    __syncthreads();
    sc[row * NN + t] = e * red;
}

extern "C" void kernel_launch(void* const* d_in, const int* in_sizes, int n_in,
                              void* d_out, int out_size) {
    const float* nodes = (const float*)d_in[0];
    const float* edges = (const float*)d_in[1];
    const float* W     = (const float*)d_in[2];
    const float* b     = (const float*)d_in[3];
    const float* ln_g  = (const float*)d_in[4];
    const float* ln_b  = (const float*)d_in[5];
    const float* W1    = (const float*)d_in[6];
    const float* b1    = (const float*)d_in[7];
    const float* W2    = (const float*)d_in[8];
    const float* b2    = (const float*)d_in[9];
    float* out = (float*)d_out;

    float *px, *pnq, *psc, *pao, *pr, *px2, *phg;
    __half *pwq;
    cudaGetSymbolAddress((void**)&px,  g_x);
    cudaGetSymbolAddress((void**)&pnq, g_nq);
    cudaGetSymbolAddress((void**)&psc, g_sc);
    cudaGetSymbolAddress((void**)&pao, g_ao);
    cudaGetSymbolAddress((void**)&pr,  g_r);
    cudaGetSymbolAddress((void**)&px2, g_x2);
    cudaGetSymbolAddress((void**)&phg, g_hg);
    cudaGetSymbolAddress((void**)&pwq, g_wq);

    cudaFuncSetAttribute(edge_mma_kernel,
                         cudaFuncAttributeMaxDynamicSharedMemorySize, EDGE_SMEM);

    prep_w<<<64, 256>>>(W, pwq);
    ln_kernel<<<NB * NN, 256>>>(nodes, ln_g, ln_b, px);
    gemm_bias<<<dim3(8, 8), 256>>>(px, W, b, pnq, DD, DD, DD, DD);
    edge_mma_kernel<<<dim3(8, NN, NB), 128, EDGE_SMEM>>>(edges, pwq, b, pnq, psc);
    softmax_kernel<<<NB * NH * NN, 256>>>(psc);
    attnv_kernel<<<dim3(4, 1, NB * NH), 256>>>(psc, pnq, pao);
    gemm_bias_res<<<dim3(8, 8), 256>>>(pao, W, b, px, pr, DD, DD, DD, DD);
    ln_kernel<<<NB * NN, 256>>>(pr, ln_g, ln_b, px2);
    gemm_gelu<<<dim3(8, 32), 256>>>(px2, W1, b1, phg, DD, FFD, FFD, DD);
    gemm_bias_res<<<dim3(8, 8), 256>>>(phg, W2, b2, px2, out, FFD, DD, DD, FFD);
}

// round 14
// speedup vs baseline: 1.2355x; 1.0556x over previous
#include <cuda_runtime.h>
#include <cuda_fp16.h>
#include <cuda_bf16.h>
#include <math.h>
#include <stdint.h>

#define NB 2
#define NN 256
#define DD 256
#define NH 8
#define FFD 1024

// ---------------- scratch (static device globals) ----------------
__device__ float g_x [NB*NN*DD];
__device__ float g_nq[NB*NN*DD];
__device__ float g_sc[(size_t)NB*NH*NN*NN];
__device__ float g_ao[NB*NN*DD];
__device__ float g_r [NB*NN*DD];
__device__ float g_x2[NB*NN*DD];
__device__ float g_hg[NB*NN*FFD];
__device__ __half g_wq [8*256*64];    // W packed   (KC=8,  N=256)
__device__ __half g_w1q[8*1024*64];   // W1 packed  (KC=8,  N=1024)
__device__ __half g_w2q[32*256*64];   // W2 packed  (KC=32, N=256)

// ---------------- helpers ----------------
__device__ __forceinline__ uint32_t smem_u32(const void* p) {
    uint32_t a;
    asm("{ .reg .u64 t; cvta.to.shared.u64 t, %1; cvt.u32.u64 %0, t; }" : "=r"(a) : "l"(p));
    return a;
}
#define CP16(dst, src) \
    asm volatile("cp.async.cg.shared.global [%0], [%1], 16;" :: "r"(dst), "l"(src))
#define CP_COMMIT() asm volatile("cp.async.commit_group;" ::: "memory")
#define CP_WAIT0() asm volatile("cp.async.wait_group 0;" ::: "memory")
#define CP_WAIT1() asm volatile("cp.async.wait_group 1;" ::: "memory")

__device__ __forceinline__ void mma16816(float* acc, const uint32_t* a,
                                         uint32_t b0, uint32_t b1) {
    asm volatile(
        "mma.sync.aligned.m16n8k16.row.col.f32.f16.f16.f32 "
        "{%0,%1,%2,%3}, {%4,%5,%6,%7}, {%8,%9}, {%0,%1,%2,%3};"
        : "+f"(acc[0]), "+f"(acc[1]), "+f"(acc[2]), "+f"(acc[3])
        : "r"(a[0]), "r"(a[1]), "r"(a[2]), "r"(a[3]), "r"(b0), "r"(b1));
}

__device__ __forceinline__ void split_f2(float2 v, uint32_t &hi, uint32_t &lo) {
    __half hx = __float2half_rn(v.x), hy = __float2half_rn(v.y);
    __half lx = __float2half_rn(v.x - __half2float(hx));
    __half ly = __float2half_rn(v.y - __half2float(hy));
    hi = (uint32_t)__half_as_ushort(hx) | ((uint32_t)__half_as_ushort(hy) << 16);
    lo = (uint32_t)__half_as_ushort(lx) | ((uint32_t)__half_as_ushort(ly) << 16);
}

// f32x2 packed helpers (for fp32 attnv GEMM)
__device__ __forceinline__ unsigned long long dup2(float x) {
    unsigned long long r;
    asm("mov.b64 %0, {%1, %1};" : "=l"(r) : "f"(x));
    return r;
}
__device__ __forceinline__ void fma2(unsigned long long &d,
                                     unsigned long long a, unsigned long long b) {
    asm("fma.rn.f32x2 %0, %1, %2, %0;" : "+l"(d) : "l"(a), "l"(b));
}
__device__ __forceinline__ void unpack2(unsigned long long v, float &lo, float &hi) {
    asm("mov.b64 {%0, %1}, %2;" : "=f"(lo), "=f"(hi) : "l"(v));
}

// ---------------- generic prep: pack B^T (K x N fp32) into fp16 hi/lo units --
// id = ((c*N + n)*8 + s*4 + p); unit halves: hi(ka),hi(ka+1),hi(ka+8),hi(ka+9),
// lo(same); ka = c*32 + s*16 + p*2, element = src[k*N + n].
__global__ void prep_pack(const float* __restrict__ src, __half* __restrict__ dst,
                          int N, int total) {
    int id = blockIdx.x * 256 + threadIdx.x;
    if (id >= total) return;
    int p = id & 3, s = (id >> 2) & 1;
    int rest = id >> 3;
    int n = rest % N, c = rest / N;
    int ka = c * 32 + s * 16 + p * 2;
    __half u[8];
    #pragma unroll
    for (int q = 0; q < 4; ++q) {
        int k = ka + (q >> 1) * 8 + (q & 1);
        float v = src[(size_t)k * N + n];
        __half h = __float2half_rn(v);
        u[q] = h;
        u[q + 4] = __float2half_rn(v - __half2float(h));
    }
    *(uint4*)(dst + (size_t)id * 8) = *(uint4*)u;
}

// ---------------- smem map shared by edge + generic mma ---------------------
#define A_PITCH 160
#define A_ST    (64*A_PITCH)      // 10240 per stage
#define B_OFF   (2*A_ST)          // 20480
#define B_ST    16384             // 128 n x 128B
#define MISC    (B_OFF + 2*B_ST)  // 53248
#define EDGE_SMEM (MISC + 1024)
#define GM_SMEM   MISC

// ---------------- fused edge GEMM (mma fp16x3), 4 CTAs/SM -------------------
// grid (x=8: jt(4)|nh(2), i=256, b=2), 128 threads (4 warps).
__global__ __launch_bounds__(128, 4) void edge_mma_kernel(
    const float* __restrict__ edges, const __half* __restrict__ wq,
    const float* __restrict__ bias, const float* __restrict__ nq,
    float* __restrict__ scores) {
    extern __shared__ char smem[];
    const uint32_t sb = smem_u32(smem);
    const int t = threadIdx.x, lane = t & 31, w = t >> 5;
    const int qp = lane & 3, lg = lane >> 2;
    const int wr = w & 1, wc = w >> 1;
    const int jt = blockIdx.x & 3, nh = blockIdx.x >> 2;
    const int i = blockIdx.y, b = blockIdx.z;
    const size_t r0 = ((size_t)(b * NN + i)) * NN + jt * 64;
    const char* eg = (const char*)(edges + r0 * DD);
    const char* wg = (const char*)wq;

    float* sBias = (float*)(smem + MISC);
    float* sNqi  = sBias + 128;
    sBias[t] = bias[nh * 128 + t];
    sNqi[t]  = nq[((size_t)(b * NN + i)) * DD + nh * 128 + t];

    #pragma unroll
    for (int c = 0; c < 2; ++c) {
        #pragma unroll
        for (int it = 0; it < 4; ++it) {
            int u = t + 128 * it, row = u >> 3, part = u & 7;
            CP16(sb + c * A_ST + row * A_PITCH + part * 16,
                 eg + (size_t)row * 1024 + c * 128 + part * 16);
        }
        #pragma unroll
        for (int it = 0; it < 8; ++it) {
            int u = t + 128 * it, n = u >> 3, u7 = u & 7;
            int us = u7 ^ ((n & 1) << 2);
            CP16(sb + B_OFF + c * B_ST + n * 128 + us * 16,
                 wg + ((size_t)(c * 256 + nh * 128 + n) * 8 + u7) * 16);
        }
        CP_COMMIT();
    }

    float acc[64];
    #pragma unroll
    for (int q = 0; q < 64; ++q) acc[q] = 0.f;

    const int rbase = wr * 32 + lg;

    #pragma unroll 1
    for (int c = 0; c < 8; ++c) {
        if (c < 7) { CP_WAIT1(); } else { CP_WAIT0(); }
        __syncthreads();
        const int st = c & 1;
        const char* abase = smem + st * A_ST;
        const char* bbase = smem + B_OFF + st * B_ST;

        #pragma unroll
        for (int s = 0; s < 2; ++s) {
            uint32_t AH[2][4], AL[2][4];
            #pragma unroll
            for (int m = 0; m < 2; ++m) {
                const char* ar = abase + (rbase + m * 16) * A_PITCH + s * 64 + qp * 8;
                float2 va = *(const float2*)(ar);
                float2 vb = *(const float2*)(ar + 8 * A_PITCH);
                float2 vc = *(const float2*)(ar + 32);
                float2 vd = *(const float2*)(ar + 8 * A_PITCH + 32);
                split_f2(va, AH[m][0], AL[m][0]);
                split_f2(vb, AH[m][1], AL[m][1]);
                split_f2(vc, AH[m][2], AL[m][2]);
                split_f2(vd, AH[m][3], AL[m][3]);
            }
            #pragma unroll
            for (int nt = 0; nt < 8; ++nt) {
                const int n = wc * 64 + nt * 8 + lg;
                const int ur = (s * 4 + qp) ^ ((n & 1) << 2);
                uint4 v = *(const uint4*)(bbase + n * 128 + ur * 16);
                #pragma unroll
                for (int m = 0; m < 2; ++m) {
                    float* ac = &acc[(m * 8 + nt) * 4];
                    mma16816(ac, AH[m], v.x, v.y);
                    mma16816(ac, AH[m], v.z, v.w);
                    mma16816(ac, AL[m], v.x, v.y);
                }
            }
        }
        __syncthreads();
        if (c < 6) {
            const int cn = c + 2;
            #pragma unroll
            for (int it = 0; it < 4; ++it) {
                int u = t + 128 * it, row = u >> 3, part = u & 7;
                CP16(sb + st * A_ST + row * A_PITCH + part * 16,
                     eg + (size_t)row * 1024 + cn * 128 + part * 16);
            }
            #pragma unroll
            for (int it = 0; it < 8; ++it) {
                int u = t + 128 * it, n = u >> 3, u7 = u & 7;
                int us = u7 ^ ((n & 1) << 2);
                CP16(sb + B_OFF + st * B_ST + n * 128 + us * 16,
                     wg + ((size_t)(cn * 256 + nh * 128 + n) * 8 + u7) * 16);
            }
            CP_COMMIT();
        }
    }

    const float* nqb = nq + ((size_t)b * NN) * DD;
    const float invs = 0.17677669529663687f;
    #pragma unroll
    for (int m = 0; m < 2; ++m) {
        const int jb = jt * 64 + wr * 32 + m * 16 + lg;
        #pragma unroll
        for (int hh = 0; hh < 2; ++hh) {
            const int h = nh * 4 + wc * 2 + hh;
            float s1 = 0.f, s2 = 0.f;
            #pragma unroll
            for (int k = 0; k < 4; ++k) {
                const int nt = hh * 4 + k;
                const int cl = wc * 64 + nt * 8 + qp * 2;
                const int cg = nh * 128 + cl;
                const float* a = &acc[(m * 8 + nt) * 4];
                float2 q1 = *(const float2*)(nqb + (size_t)jb * DD + cg);
                float2 q2 = *(const float2*)(nqb + (size_t)(jb + 8) * DD + cg);
                float bi0 = sBias[cl], bi1 = sBias[cl + 1];
                float ni0 = sNqi[cl],  ni1 = sNqi[cl + 1];
                float e;
                e = a[0] + bi0; s1 += (e + ni0) * (e + q1.x);
                e = a[1] + bi1; s1 += (e + ni1) * (e + q1.y);
                e = a[2] + bi0; s2 += (e + ni0) * (e + q2.x);
                e = a[3] + bi1; s2 += (e + ni1) * (e + q2.y);
            }
            s1 += __shfl_xor_sync(0xffffffffu, s1, 1);
            s1 += __shfl_xor_sync(0xffffffffu, s1, 2);
            s2 += __shfl_xor_sync(0xffffffffu, s2, 1);
            s2 += __shfl_xor_sync(0xffffffffu, s2, 2);
            if (qp == 0) {
                float* sp = scores + (((size_t)(b * NH + h)) << 16) + (size_t)i * NN;
                sp[jb]     = 10.0f * tanhf(s1 * invs);
                sp[jb + 8] = 10.0f * tanhf(s2 * invs);
            }
        }
    }
}

// ---------------- generic mma GEMM: C = A@B (+bias)(+res | gelu) ------------
// grid (N/128, M/64), 128 threads. mode: 0=bias, 1=bias+res, 2=bias+gelu.
__global__ __launch_bounds__(128, 4) void gemm_mma(
    const float* __restrict__ A, const __half* __restrict__ Bq,
    const float* __restrict__ bias, const float* __restrict__ res,
    float* __restrict__ C, int N, int K, int mode) {
    extern __shared__ char smem[];
    const uint32_t sb = smem_u32(smem);
    const int t = threadIdx.x, lane = t & 31, w = t >> 5;
    const int qp = lane & 3, lg = lane >> 2;
    const int wr = w & 1, wc = w >> 1;
    const int bx = blockIdx.x, by = blockIdx.y;
    const int KC = K >> 5;
    const char* bqg = (const char*)Bq;

    #pragma unroll
    for (int c = 0; c < 2; ++c) {
        #pragma unroll
        for (int it = 0; it < 4; ++it) {
            int u = t + 128 * it, row = u >> 3, part = u & 7;
            CP16(sb + c * A_ST + row * A_PITCH + part * 16,
                 (const char*)(A + (size_t)(by * 64 + row) * K + c * 32) + part * 16);
        }
        #pragma unroll
        for (int it = 0; it < 8; ++it) {
            int u = t + 128 * it, n = u >> 3, u7 = u & 7;
            int us = u7 ^ ((n & 1) << 2);
            CP16(sb + B_OFF + c * B_ST + n * 128 + us * 16,
                 bqg + ((size_t)((size_t)c * N + bx * 128 + n) * 8 + u7) * 16);
        }
        CP_COMMIT();
    }

    float acc[64];
    #pragma unroll
    for (int q = 0; q < 64; ++q) acc[q] = 0.f;

    const int rbase = wr * 32 + lg;

    #pragma unroll 1
    for (int c = 0; c < KC; ++c) {
        if (c < KC - 1) { CP_WAIT1(); } else { CP_WAIT0(); }
        __syncthreads();
        const int st = c & 1;
        const char* abase = smem + st * A_ST;
        const char* bbase = smem + B_OFF + st * B_ST;

        #pragma unroll
        for (int s = 0; s < 2; ++s) {
            uint32_t AH[2][4], AL[2][4];
            #pragma unroll
            for (int m = 0; m < 2; ++m) {
                const char* ar = abase + (rbase + m * 16) * A_PITCH + s * 64 + qp * 8;
                float2 va = *(const float2*)(ar);
                float2 vb = *(const float2*)(ar + 8 * A_PITCH);
                float2 vc = *(const float2*)(ar + 32);
                float2 vd = *(const float2*)(ar + 8 * A_PITCH + 32);
                split_f2(va, AH[m][0], AL[m][0]);
                split_f2(vb, AH[m][1], AL[m][1]);
                split_f2(vc, AH[m][2], AL[m][2]);
                split_f2(vd, AH[m][3], AL[m][3]);
            }
            #pragma unroll
            for (int nt = 0; nt < 8; ++nt) {
                const int n = wc * 64 + nt * 8 + lg;
                const int ur = (s * 4 + qp) ^ ((n & 1) << 2);
                uint4 v = *(const uint4*)(bbase + n * 128 + ur * 16);
                #pragma unroll
                for (int m = 0; m < 2; ++m) {
                    float* ac = &acc[(m * 8 + nt) * 4];
                    mma16816(ac, AH[m], v.x, v.y);
                    mma16816(ac, AH[m], v.z, v.w);
                    mma16816(ac, AL[m], v.x, v.y);
                }
            }
        }
        __syncthreads();
        if (c < KC - 2) {
            const int cn = c + 2;
            #pragma unroll
            for (int it = 0; it < 4; ++it) {
                int u = t + 128 * it, row = u >> 3, part = u & 7;
                CP16(sb + st * A_ST + row * A_PITCH + part * 16,
                     (const char*)(A + (size_t)(by * 64 + row) * K + cn * 32) + part * 16);
            }
            #pragma unroll
            for (int it = 0; it < 8; ++it) {
                int u = t + 128 * it, n = u >> 3, u7 = u & 7;
                int us = u7 ^ ((n & 1) << 2);
                CP16(sb + B_OFF + st * B_ST + n * 128 + us * 16,
                     bqg + ((size_t)((size_t)cn * N + bx * 128 + n) * 8 + u7) * 16);
            }
            CP_COMMIT();
        }
    }

    // epilogue
    #pragma unroll
    for (int nt = 0; nt < 8; ++nt) {
        const int col = bx * 128 + wc * 64 + nt * 8 + qp * 2;
        const float b0 = bias[col], b1 = bias[col + 1];
        #pragma unroll
        for (int m = 0; m < 2; ++m) {
            const int row0 = by * 64 + wr * 32 + m * 16 + lg;
            const float* a = &acc[(m * 8 + nt) * 4];
            float v00 = a[0] + b0, v01 = a[1] + b1;
            float v10 = a[2] + b0, v11 = a[3] + b1;
            if (mode == 2) {
                v00 = 0.5f * v00 * (1.0f + erff(v00 * 0.70710678118654752f));
                v01 = 0.5f * v01 * (1.0f + erff(v01 * 0.70710678118654752f));
                v10 = 0.5f * v10 * (1.0f + erff(v10 * 0.70710678118654752f));
                v11 = 0.5f * v11 * (1.0f + erff(v11 * 0.70710678118654752f));
            } else if (mode == 1) {
                float2 r0 = *(const float2*)(res + (size_t)row0 * N + col);
                float2 r1 = *(const float2*)(res + (size_t)(row0 + 8) * N + col);
                v00 += r0.x; v01 += r0.y; v10 += r1.x; v11 += r1.y;
            }
            float2 o0 = {v00, v01}, o1 = {v10, v11};
            *(float2*)(C + (size_t)row0 * N + col) = o0;
            *(float2*)(C + (size_t)(row0 + 8) * N + col) = o1;
        }
    }
}

// ---------------- LayerNorm ----------------
__global__ void ln_kernel(const float* __restrict__ in,
                          const float* __restrict__ gam,
                          const float* __restrict__ bet,
                          float* __restrict__ out) {
    __shared__ float sh[16];
    __shared__ float stats[2];
    const int row = blockIdx.x, t = threadIdx.x;
    float v = in[(size_t)row * DD + t];
    float s = v, sq = v * v;
    #pragma unroll
    for (int o = 16; o; o >>= 1) {
        s  += __shfl_down_sync(0xffffffffu, s,  o);
        sq += __shfl_down_sync(0xffffffffu, sq, o);
    }
    if ((t & 31) == 0) { sh[t >> 5] = s; sh[(t >> 5) + 8] = sq; }
    __syncthreads();
    if (t == 0) {
        float ts = 0.f, tq = 0.f;
        #pragma unroll
        for (int k = 0; k < 8; ++k) { ts += sh[k]; tq += sh[k + 8]; }
        float mu = ts * (1.0f / 256.0f);
        float var = tq * (1.0f / 256.0f) - mu * mu;
        stats[0] = mu; stats[1] = rsqrtf(var + 1e-5f);
    }
    __syncthreads();
    out[(size_t)row * DD + t] = (v - stats[0]) * stats[1] * gam[t] + bet[t];
}

// ---------------- fp32 64x32 GEMM tile (f32x2), for attnv -------------------
__device__ __forceinline__ void gemm_tile64x32(
    const float* __restrict__ A, const float* __restrict__ B,
    int lda, int ldb, int K, int m0, int n0, float acc[8]) {
    __shared__ __align__(16) float AsT[32][68];
    __shared__ float Bs[32][33];
    const int t = threadIdx.x, tn = t & 31, tg = t >> 5;
    unsigned long long acc2[4] = {0ull, 0ull, 0ull, 0ull};
    for (int k0 = 0; k0 < K; k0 += 32) {
        #pragma unroll
        for (int ph = 0; ph < 2; ++ph) {
            int flat = t + 256 * ph;
            int m = flat >> 3, kc = (flat & 7) << 2;
            float4 av = *(const float4*)(A + (size_t)(m0 + m) * lda + k0 + kc);
            AsT[kc + 0][m] = av.x; AsT[kc + 1][m] = av.y;
            AsT[kc + 2][m] = av.z; AsT[kc + 3][m] = av.w;
        }
        {
            int kr = t >> 3, nc = (t & 7) << 2;
            float4 bv = *(const float4*)(B + (size_t)(k0 + kr) * ldb + n0 + nc);
            Bs[kr][nc + 0] = bv.x; Bs[kr][nc + 1] = bv.y;
            Bs[kr][nc + 2] = bv.z; Bs[kr][nc + 3] = bv.w;
        }
        __syncthreads();
        #pragma unroll
        for (int kk = 0; kk < 32; ++kk) {
            ulonglong2 a01 = *(const ulonglong2*)&AsT[kk][tg * 8];
            ulonglong2 a23 = *(const ulonglong2*)&AsT[kk][tg * 8 + 4];
            unsigned long long b2 = dup2(Bs[kk][tn]);
            fma2(acc2[0], a01.x, b2);
            fma2(acc2[1], a01.y, b2);
            fma2(acc2[2], a23.x, b2);
            fma2(acc2[3], a23.y, b2);
        }
        __syncthreads();
    }
    unpack2(acc2[0], acc[0], acc[1]);
    unpack2(acc2[1], acc[2], acc[3]);
    unpack2(acc2[2], acc[4], acc[5]);
    unpack2(acc2[3], acc[6], acc[7]);
}

__global__ __launch_bounds__(256) void attnv_kernel(
    const float* __restrict__ scores, const float* __restrict__ nq,
    float* __restrict__ ao) {
    const int z = blockIdx.z, b = z >> 3, h = z & 7;
    const float* A = scores + (size_t)z * NN * NN;
    const float* B = nq + (size_t)b * NN * DD + h * 32;
    float acc[8];
    const int m0 = blockIdx.x * 64;
    gemm_tile64x32(A, B, NN, DD, NN, m0, 0, acc);
    const int tn = threadIdx.x & 31, tg = threadIdx.x >> 5;
    #pragma unroll
    for (int q = 0; q < 8; ++q)
        ao[((size_t)b * NN + (m0 + tg * 8 + q)) * DD + h * 32 + tn] = acc[q];
}

// ---------------- softmax (last dim 256, in place) ----------------
__global__ void softmax_kernel(float* __restrict__ sc) {
    __shared__ float sh[8];
    __shared__ float red;
    const size_t row = blockIdx.x;
    const int t = threadIdx.x;
    float v = sc[row * NN + t];
    float m = v;
    #pragma unroll
    for (int o = 16; o; o >>= 1) m = fmaxf(m, __shfl_xor_sync(0xffffffffu, m, o));
    if ((t & 31) == 0) sh[t >> 5] = m;
    __syncthreads();
    if (t == 0) {
        float mm = sh[0];
        #pragma unroll
        for (int w = 1; w < 8; ++w) mm = fmaxf(mm, sh[w]);
        red = mm;
    }
    __syncthreads();
    m = red;
    float e = expf(v - m);
    float s = e;
    #pragma unroll
    for (int o = 16; o; o >>= 1) s += __shfl_xor_sync(0xffffffffu, s, o);
    __syncthreads();
    if ((t & 31) == 0) sh[t >> 5] = s;
    __syncthreads();
    if (t == 0) {
        float ss = 0.f;
        #pragma unroll
        for (int w = 0; w < 8; ++w) ss += sh[w];
        red = 1.0f / ss;
    }
    __syncthreads();
    sc[row * NN + t] = e * red;
}

extern "C" void kernel_launch(void* const* d_in, const int* in_sizes, int n_in,
                              void* d_out, int out_size) {
    const float* nodes = (const float*)d_in[0];
    const float* edges = (const float*)d_in[1];
    const float* W     = (const float*)d_in[2];
    const float* b     = (const float*)d_in[3];
    const float* ln_g  = (const float*)d_in[4];
    const float* ln_b  = (const float*)d_in[5];
    const float* W1    = (const float*)d_in[6];
    const float* b1    = (const float*)d_in[7];
    const float* W2    = (const float*)d_in[8];
    const float* b2    = (const float*)d_in[9];
    float* out = (float*)d_out;

    float *px, *pnq, *psc, *pao, *pr, *px2, *phg;
    __half *pwq, *pw1q, *pw2q;
    cudaGetSymbolAddress((void**)&px,  g_x);
    cudaGetSymbolAddress((void**)&pnq, g_nq);
    cudaGetSymbolAddress((void**)&psc, g_sc);
    cudaGetSymbolAddress((void**)&pao, g_ao);
    cudaGetSymbolAddress((void**)&pr,  g_r);
    cudaGetSymbolAddress((void**)&px2, g_x2);
    cudaGetSymbolAddress((void**)&phg, g_hg);
    cudaGetSymbolAddress((void**)&pwq, g_wq);
    cudaGetSymbolAddress((void**)&pw1q, g_w1q);
    cudaGetSymbolAddress((void**)&pw2q, g_w2q);

    cudaFuncSetAttribute(edge_mma_kernel,
                         cudaFuncAttributeMaxDynamicSharedMemorySize, EDGE_SMEM);
    cudaFuncSetAttribute(gemm_mma,
                         cudaFuncAttributeMaxDynamicSharedMemorySize, GM_SMEM);

    prep_pack<<<64, 256>>>(W,  pwq,  256,  16384);
    prep_pack<<<256, 256>>>(W1, pw1q, 1024, 65536);
    prep_pack<<<256, 256>>>(W2, pw2q, 256,  65536);
    ln_kernel<<<NB * NN, 256>>>(nodes, ln_g, ln_b, px);
    gemm_mma<<<dim3(2, 8), 128, GM_SMEM>>>(px, pwq, b, nullptr, pnq, 256, 256, 0);
    edge_mma_kernel<<<dim3(8, NN, NB), 128, EDGE_SMEM>>>(edges, pwq, b, pnq, psc);
    softmax_kernel<<<NB * NH * NN, 256>>>(psc);
    attnv_kernel<<<dim3(4, 1, NB * NH), 256>>>(psc, pnq, pao);
    gemm_mma<<<dim3(2, 8), 128, GM_SMEM>>>(pao, pwq, b, px, pr, 256, 256, 1);
    ln_kernel<<<NB * NN, 256>>>(pr, ln_g, ln_b, px2);
    gemm_mma<<<dim3(8, 8), 128, GM_SMEM>>>(px2, pw1q, b1, nullptr, phg, 1024, 256, 2);
    gemm_mma<<<dim3(2, 8), 128, GM_SMEM>>>(phg, pw2q, b2, px2, out, 256, 1024, 1);
}

// round 16
// speedup vs baseline: 1.2741x; 1.0312x over previous
#include <cuda_runtime.h>
#include <cuda_fp16.h>
#include <cuda_bf16.h>
#include <math.h>
#include <stdint.h>

#define NB 2
#define NN 256
#define DD 256
#define NH 8
#define FFD 1024

// ---------------- scratch (static device globals) ----------------
__device__ float g_x [NB*NN*DD];
__device__ float g_nq[NB*NN*DD];
__device__ float g_sc[(size_t)NB*NH*NN*NN];
__device__ float g_ao[NB*NN*DD];
__device__ float g_r [NB*NN*DD];
__device__ float g_x2[NB*NN*DD];
__device__ float g_hg[NB*NN*FFD];
__device__ __half g_wq [8*256*64];    // W packed   (KC=8,  N=256)
__device__ __half g_w1q[8*1024*64];   // W1 packed  (KC=8,  N=1024)
__device__ __half g_w2q[32*256*64];   // W2 packed  (KC=32, N=256)

// ---------------- helpers ----------------
__device__ __forceinline__ uint32_t smem_u32(const void* p) {
    uint32_t a;
    asm("{ .reg .u64 t; cvta.to.shared.u64 t, %1; cvt.u32.u64 %0, t; }" : "=r"(a) : "l"(p));
    return a;
}
#define CP16(dst, src) \
    asm volatile("cp.async.cg.shared.global [%0], [%1], 16;" :: "r"(dst), "l"(src))
#define CP_COMMIT() asm volatile("cp.async.commit_group;" ::: "memory")
#define CP_WAIT0() asm volatile("cp.async.wait_group 0;" ::: "memory")
#define CP_WAIT1() asm volatile("cp.async.wait_group 1;" ::: "memory")

#define MBAR_INIT(mb, cnt) \
    asm volatile("mbarrier.init.shared.b64 [%0], %1;" :: "r"((uint32_t)(mb)), "r"((uint32_t)(cnt)) : "memory")
#define MBAR_ARRIVE(mb) \
    asm volatile("mbarrier.arrive.shared.b64 _, [%0];" :: "r"((uint32_t)(mb)) : "memory")
// FIX R15: .noinc — default form self-balances (inc@issue, dec@complete) and
// the barrier phase never completes -> deadlock. noinc counts against init cnt.
#define CP_MBAR_ARRIVE(mb) \
    asm volatile("cp.async.mbarrier.arrive.noinc.shared::cta.b64 [%0];" :: "r"((uint32_t)(mb)) : "memory")
// FIX R15: acquire ordering on the wait (matches proven ptx_helpers macro).
#define MBAR_WAIT(mb, ph) do { \
    uint32_t _m = (uint32_t)(mb); uint32_t _p = (uint32_t)(ph); uint32_t _d; \
    asm volatile("{\n\t.reg .pred p;\n\t" \
        "mbarrier.try_wait.parity.acquire.cta.shared::cta.b64 p, [%1], %2;\n\t" \
        "selp.b32 %0, 1, 0, p;\n\t}" : "=r"(_d) : "r"(_m), "r"(_p) : "memory"); \
    if (!_d) { \
        asm volatile("{\n\t.reg .pred P1;\n\t" \
            "WL_%=:\n\t" \
            "mbarrier.try_wait.parity.acquire.cta.shared::cta.b64 P1, [%0], %1, 0x989680;\n\t" \
            "@P1 bra.uni WD_%=;\n\t" \
            "bra.uni WL_%=;\n\t" \
            "WD_%=:\n\t}" :: "r"(_m), "r"(_p) : "memory"); \
    } } while (0)

__device__ __forceinline__ void mma16816(float* acc, const uint32_t* a,
                                         uint32_t b0, uint32_t b1) {
    asm volatile(
        "mma.sync.aligned.m16n8k16.row.col.f32.f16.f16.f32 "
        "{%0,%1,%2,%3}, {%4,%5,%6,%7}, {%8,%9}, {%0,%1,%2,%3};"
        : "+f"(acc[0]), "+f"(acc[1]), "+f"(acc[2]), "+f"(acc[3])
        : "r"(a[0]), "r"(a[1]), "r"(a[2]), "r"(a[3]), "r"(b0), "r"(b1));
}

__device__ __forceinline__ void split_f2(float2 v, uint32_t &hi, uint32_t &lo) {
    __half hx = __float2half_rn(v.x), hy = __float2half_rn(v.y);
    __half lx = __float2half_rn(v.x - __half2float(hx));
    __half ly = __float2half_rn(v.y - __half2float(hy));
    hi = (uint32_t)__half_as_ushort(hx) | ((uint32_t)__half_as_ushort(hy) << 16);
    lo = (uint32_t)__half_as_ushort(lx) | ((uint32_t)__half_as_ushort(ly) << 16);
}

// f32x2 packed helpers (for fp32 attnv GEMM)
__device__ __forceinline__ unsigned long long dup2(float x) {
    unsigned long long r;
    asm("mov.b64 %0, {%1, %1};" : "=l"(r) : "f"(x));
    return r;
}
__device__ __forceinline__ void fma2(unsigned long long &d,
                                     unsigned long long a, unsigned long long b) {
    asm("fma.rn.f32x2 %0, %1, %2, %0;" : "+l"(d) : "l"(a), "l"(b));
}
__device__ __forceinline__ void unpack2(unsigned long long v, float &lo, float &hi) {
    asm("mov.b64 {%0, %1}, %2;" : "=f"(lo), "=f"(hi) : "l"(v));
}

// ---------------- generic prep: pack B^T (K x N fp32) into fp16 hi/lo units --
__global__ void prep_pack(const float* __restrict__ src, __half* __restrict__ dst,
                          int N, int total) {
    int id = blockIdx.x * 256 + threadIdx.x;
    if (id >= total) return;
    int p = id & 3, s = (id >> 2) & 1;
    int rest = id >> 3;
    int n = rest % N, c = rest / N;
    int ka = c * 32 + s * 16 + p * 2;
    __half u[8];
    #pragma unroll
    for (int q = 0; q < 4; ++q) {
        int k = ka + (q >> 1) * 8 + (q & 1);
        float v = src[(size_t)k * N + n];
        __half h = __float2half_rn(v);
        u[q] = h;
        u[q + 4] = __float2half_rn(v - __half2float(h));
    }
    *(uint4*)(dst + (size_t)id * 8) = *(uint4*)u;
}

// ---------------- smem maps ---------------------
#define A_PITCH 160
#define A_ST    (64*A_PITCH)      // 10240 per stage (edge)
#define B_OFF   (2*A_ST)          // 20480
#define B_ST    16384             // 128 n x 128B
#define MISC    (B_OFF + 2*B_ST)  // 53248
#define EDGE_SMEM (MISC + 1024 + 64)

// gemm_mma32 (M-tile 32): A 32x160 per stage at 0/5120; B at 10240/26624
#define A32_ST  5120
#define B32_OFF 10240
#define GM_SMEM 43008

// ---------------- fused edge GEMM (mma fp16x3), mbarrier pipeline -----------
// grid (x=8: jt(4)|nh(2), i=256, b=2), 128 threads (4 warps), 4 CTAs/SM.
__global__ __launch_bounds__(128, 4) void edge_mma_kernel(
    const float* __restrict__ edges, const __half* __restrict__ wq,
    const float* __restrict__ bias, const float* __restrict__ nq,
    float* __restrict__ scores) {
    extern __shared__ char smem[];
    const uint32_t sb = smem_u32(smem);
    const int t = threadIdx.x, lane = t & 31, w = t >> 5;
    const int qp = lane & 3, lg = lane >> 2;
    const int wr = w & 1, wc = w >> 1;
    const int jt = blockIdx.x & 3, nh = blockIdx.x >> 2;
    const int i = blockIdx.y, b = blockIdx.z;
    const size_t r0 = ((size_t)(b * NN + i)) * NN + jt * 64;
    const char* eg = (const char*)(edges + r0 * DD);
    const char* wg = (const char*)wq;

    const uint32_t mFull0  = sb + MISC + 1024;
    const uint32_t mEmpty0 = sb + MISC + 1040;

    float* sBias = (float*)(smem + MISC);
    float* sNqi  = sBias + 128;
    sBias[t] = bias[nh * 128 + t];
    sNqi[t]  = nq[((size_t)(b * NN + i)) * DD + nh * 128 + t];
    if (t == 0) {
        MBAR_INIT(mFull0,      128); MBAR_INIT(mFull0 + 8,  128);
        MBAR_INIT(mEmpty0,     128); MBAR_INIT(mEmpty0 + 8, 128);
    }
    __syncthreads();
    MBAR_ARRIVE(mEmpty0);          // pre-complete empty phase 0 (both stages)
    MBAR_ARRIVE(mEmpty0 + 8);

    // prologue: chunks 0,1 -> stages 0,1
    #pragma unroll
    for (int c = 0; c < 2; ++c) {
        #pragma unroll
        for (int it = 0; it < 4; ++it) {
            int u = t + 128 * it, row = u >> 3, part = u & 7;
            CP16(sb + c * A_ST + row * A_PITCH + part * 16,
                 eg + (size_t)row * 1024 + c * 128 + part * 16);
        }
        #pragma unroll
        for (int it = 0; it < 8; ++it) {
            int u = t + 128 * it, n = u >> 3, u7 = u & 7;
            int us = u7 ^ ((n & 1) << 2);
            CP16(sb + B_OFF + c * B_ST + n * 128 + us * 16,
                 wg + ((size_t)(c * 256 + nh * 128 + n) * 8 + u7) * 16);
        }
        CP_MBAR_ARRIVE(mFull0 + c * 8);
    }

    float acc[64];
    #pragma unroll
    for (int q = 0; q < 64; ++q) acc[q] = 0.f;

    const int rbase = wr * 32 + lg;

    #pragma unroll 1
    for (int c = 0; c < 8; ++c) {
        const int st = c & 1;
        const uint32_t mF = mFull0 + st * 8, mE = mEmpty0 + st * 8;
        MBAR_WAIT(mF, (c >> 1) & 1);
        const char* abase = smem + st * A_ST;
        const char* bbase = smem + B_OFF + st * B_ST;

        #pragma unroll
        for (int s = 0; s < 2; ++s) {
            uint32_t AH[2][4], AL[2][4];
            #pragma unroll
            for (int m = 0; m < 2; ++m) {
                const char* ar = abase + (rbase + m * 16) * A_PITCH + s * 64 + qp * 8;
                float2 va = *(const float2*)(ar);
                float2 vb = *(const float2*)(ar + 8 * A_PITCH);
                float2 vc = *(const float2*)(ar + 32);
                float2 vd = *(const float2*)(ar + 8 * A_PITCH + 32);
                split_f2(va, AH[m][0], AL[m][0]);
                split_f2(vb, AH[m][1], AL[m][1]);
                split_f2(vc, AH[m][2], AL[m][2]);
                split_f2(vd, AH[m][3], AL[m][3]);
            }
            #pragma unroll
            for (int nt = 0; nt < 8; ++nt) {
                const int n = wc * 64 + nt * 8 + lg;
                const int ur = (s * 4 + qp) ^ ((n & 1) << 2);
                uint4 v = *(const uint4*)(bbase + n * 128 + ur * 16);
                #pragma unroll
                for (int m = 0; m < 2; ++m) {
                    float* ac = &acc[(m * 8 + nt) * 4];
                    mma16816(ac, AH[m], v.x, v.y);
                    mma16816(ac, AH[m], v.z, v.w);
                    mma16816(ac, AL[m], v.x, v.y);
                }
            }
        }
        MBAR_ARRIVE(mE);                       // done reading stage st
        if (c < 6) {
            MBAR_WAIT(mE, ((c >> 1) + 1) & 1); // all readers of chunk c done
            const int cn = c + 2;
            #pragma unroll
            for (int it = 0; it < 4; ++it) {
                int u = t + 128 * it, row = u >> 3, part = u & 7;
                CP16(sb + st * A_ST + row * A_PITCH + part * 16,
                     eg + (size_t)row * 1024 + cn * 128 + part * 16);
            }
            #pragma unroll
            for (int it = 0; it < 8; ++it) {
                int u = t + 128 * it, n = u >> 3, u7 = u & 7;
                int us = u7 ^ ((n & 1) << 2);
                CP16(sb + B_OFF + st * B_ST + n * 128 + us * 16,
                     wg + ((size_t)(cn * 256 + nh * 128 + n) * 8 + u7) * 16);
            }
            CP_MBAR_ARRIVE(mF);
        }
    }

    const float* nqb = nq + ((size_t)b * NN) * DD;
    const float invs = 0.17677669529663687f;
    #pragma unroll
    for (int m = 0; m < 2; ++m) {
        const int jb = jt * 64 + wr * 32 + m * 16 + lg;
        #pragma unroll
        for (int hh = 0; hh < 2; ++hh) {
            const int h = nh * 4 + wc * 2 + hh;
            float s1 = 0.f, s2 = 0.f;
            #pragma unroll
            for (int k = 0; k < 4; ++k) {
                const int nt = hh * 4 + k;
                const int cl = wc * 64 + nt * 8 + qp * 2;
                const int cg = nh * 128 + cl;
                const float* a = &acc[(m * 8 + nt) * 4];
                float2 q1 = *(const float2*)(nqb + (size_t)jb * DD + cg);
                float2 q2 = *(const float2*)(nqb + (size_t)(jb + 8) * DD + cg);
                float bi0 = sBias[cl], bi1 = sBias[cl + 1];
                float ni0 = sNqi[cl],  ni1 = sNqi[cl + 1];
                float e;
                e = a[0] + bi0; s1 += (e + ni0) * (e + q1.x);
                e = a[1] + bi1; s1 += (e + ni1) * (e + q1.y);
                e = a[2] + bi0; s2 += (e + ni0) * (e + q2.x);
                e = a[3] + bi1; s2 += (e + ni1) * (e + q2.y);
            }
            s1 += __shfl_xor_sync(0xffffffffu, s1, 1);
            s1 += __shfl_xor_sync(0xffffffffu, s1, 2);
            s2 += __shfl_xor_sync(0xffffffffu, s2, 1);
            s2 += __shfl_xor_sync(0xffffffffu, s2, 2);
            if (qp == 0) {
                float* sp = scores + (((size_t)(b * NH + h)) << 16) + (size_t)i * NN;
                sp[jb]     = 10.0f * tanhf(s1 * invs);
                sp[jb + 8] = 10.0f * tanhf(s2 * invs);
            }
        }
    }
}

// ---------------- generic mma GEMM, M-tile 32: C = A@B (+bias)(+res|gelu) ---
// grid (N/128, M/32), 64 threads (2 warps). mode: 0=bias, 1=+res, 2=+gelu.
__global__ __launch_bounds__(64, 5) void gemm_mma32(
    const float* __restrict__ A, const __half* __restrict__ Bq,
    const float* __restrict__ bias, const float* __restrict__ res,
    float* __restrict__ C, int N, int K, int mode) {
    extern __shared__ char smem[];
    const uint32_t sb = smem_u32(smem);
    const int t = threadIdx.x, lane = t & 31, wc = t >> 5;
    const int qp = lane & 3, lg = lane >> 2;
    const int bx = blockIdx.x, by = blockIdx.y;
    const int KC = K >> 5;
    const char* bqg = (const char*)Bq;

    #pragma unroll
    for (int c = 0; c < 2; ++c) {
        #pragma unroll
        for (int it = 0; it < 4; ++it) {
            int u = t + 64 * it, row = u >> 3, part = u & 7;
            CP16(sb + c * A32_ST + row * A_PITCH + part * 16,
                 (const char*)(A + (size_t)(by * 32 + row) * K + c * 32) + part * 16);
        }
        #pragma unroll
        for (int it = 0; it < 16; ++it) {
            int u = t + 64 * it, n = u >> 3, u7 = u & 7;
            int us = u7 ^ ((n & 1) << 2);
            CP16(sb + B32_OFF + c * B_ST + n * 128 + us * 16,
                 bqg + ((size_t)((size_t)c * N + bx * 128 + n) * 8 + u7) * 16);
        }
        CP_COMMIT();
    }

    float acc[64];
    #pragma unroll
    for (int q = 0; q < 64; ++q) acc[q] = 0.f;

    #pragma unroll 1
    for (int c = 0; c < KC; ++c) {
        if (c < KC - 1) { CP_WAIT1(); } else { CP_WAIT0(); }
        __syncthreads();
        const int st = c & 1;
        const char* abase = smem + st * A32_ST;
        const char* bbase = smem + B32_OFF + st * B_ST;

        #pragma unroll
        for (int s = 0; s < 2; ++s) {
            uint32_t AH[2][4], AL[2][4];
            #pragma unroll
            for (int m = 0; m < 2; ++m) {
                const char* ar = abase + (lg + m * 16) * A_PITCH + s * 64 + qp * 8;
                float2 va = *(const float2*)(ar);
                float2 vb = *(const float2*)(ar + 8 * A_PITCH);
                float2 vc = *(const float2*)(ar + 32);
                float2 vd = *(const float2*)(ar + 8 * A_PITCH + 32);
                split_f2(va, AH[m][0], AL[m][0]);
                split_f2(vb, AH[m][1], AL[m][1]);
                split_f2(vc, AH[m][2], AL[m][2]);
                split_f2(vd, AH[m][3], AL[m][3]);
            }
            #pragma unroll
            for (int nt = 0; nt < 8; ++nt) {
                const int n = wc * 64 + nt * 8 + lg;
                const int ur = (s * 4 + qp) ^ ((n & 1) << 2);
                uint4 v = *(const uint4*)(bbase + n * 128 + ur * 16);
                #pragma unroll
                for (int m = 0; m < 2; ++m) {
                    float* ac = &acc[(m * 8 + nt) * 4];
                    mma16816(ac, AH[m], v.x, v.y);
                    mma16816(ac, AH[m], v.z, v.w);
                    mma16816(ac, AL[m], v.x, v.y);
                }
            }
        }
        __syncthreads();
        if (c < KC - 2) {
            const int cn = c + 2;
            #pragma unroll
            for (int it = 0; it < 4; ++it) {
                int u = t + 64 * it, row = u >> 3, part = u & 7;
                CP16(sb + st * A32_ST + row * A_PITCH + part * 16,
                     (const char*)(A + (size_t)(by * 32 + row) * K + cn * 32) + part * 16);
            }
            #pragma unroll
            for (int it = 0; it < 16; ++it) {
                int u = t + 64 * it, n = u >> 3, u7 = u & 7;
                int us = u7 ^ ((n & 1) << 2);
                CP16(sb + B32_OFF + st * B_ST + n * 128 + us * 16,
                     bqg + ((size_t)((size_t)cn * N + bx * 128 + n) * 8 + u7) * 16);
            }
            CP_COMMIT();
        }
    }

    #pragma unroll
    for (int nt = 0; nt < 8; ++nt) {
        const int col = bx * 128 + wc * 64 + nt * 8 + qp * 2;
        const float b0 = bias[col], b1 = bias[col + 1];
        #pragma unroll
        for (int m = 0; m < 2; ++m) {
            const int row0 = by * 32 + m * 16 + lg;
            const float* a = &acc[(m * 8 + nt) * 4];
            float v00 = a[0] + b0, v01 = a[1] + b1;
            float v10 = a[2] + b0, v11 = a[3] + b1;
            if (mode == 2) {
                v00 = 0.5f * v00 * (1.0f + erff(v00 * 0.70710678118654752f));
                v01 = 0.5f * v01 * (1.0f + erff(v01 * 0.70710678118654752f));
                v10 = 0.5f * v10 * (1.0f + erff(v10 * 0.70710678118654752f));
                v11 = 0.5f * v11 * (1.0f + erff(v11 * 0.70710678118654752f));
            } else if (mode == 1) {
                float2 r0 = *(const float2*)(res + (size_t)row0 * N + col);
                float2 r1 = *(const float2*)(res + (size_t)(row0 + 8) * N + col);
                v00 += r0.x; v01 += r0.y; v10 += r1.x; v11 += r1.y;
            }
            float2 o0 = {v00, v01}, o1 = {v10, v11};
            *(float2*)(C + (size_t)row0 * N + col) = o0;
            *(float2*)(C + (size_t)(row0 + 8) * N + col) = o1;
        }
    }
}

// ---------------- LayerNorm ----------------
__global__ void ln_kernel(const float* __restrict__ in,
                          const float* __restrict__ gam,
                          const float* __restrict__ bet,
                          float* __restrict__ out) {
    __shared__ float sh[16];
    __shared__ float stats[2];
    const int row = blockIdx.x, t = threadIdx.x;
    float v = in[(size_t)row * DD + t];
    float s = v, sq = v * v;
    #pragma unroll
    for (int o = 16; o; o >>= 1) {
        s  += __shfl_down_sync(0xffffffffu, s,  o);
        sq += __shfl_down_sync(0xffffffffu, sq, o);
    }
    if ((t & 31) == 0) { sh[t >> 5] = s; sh[(t >> 5) + 8] = sq; }
    __syncthreads();
    if (t == 0) {
        float ts = 0.f, tq = 0.f;
        #pragma unroll
        for (int k = 0; k < 8; ++k) { ts += sh[k]; tq += sh[k + 8]; }
        float mu = ts * (1.0f / 256.0f);
        float var = tq * (1.0f / 256.0f) - mu * mu;
        stats[0] = mu; stats[1] = rsqrtf(var + 1e-5f);
    }
    __syncthreads();
    out[(size_t)row * DD + t] = (v - stats[0]) * stats[1] * gam[t] + bet[t];
}

// ---------------- fp32 64x32 GEMM tile (f32x2), for attnv -------------------
__device__ __forceinline__ void gemm_tile64x32(
    const float* __restrict__ A, const float* __restrict__ B,
    int lda, int ldb, int K, int m0, int n0, float acc[8]) {
    __shared__ __align__(16) float AsT[32][68];
    __shared__ float Bs[32][33];
    const int t = threadIdx.x, tn = t & 31, tg = t >> 5;
    unsigned long long acc2[4] = {0ull, 0ull, 0ull, 0ull};
    for (int k0 = 0; k0 < K; k0 += 32) {
        #pragma unroll
        for (int ph = 0; ph < 2; ++ph) {
            int flat = t + 256 * ph;
            int m = flat >> 3, kc = (flat & 7) << 2;
            float4 av = *(const float4*)(A + (size_t)(m0 + m) * lda + k0 + kc);
            AsT[kc + 0][m] = av.x; AsT[kc + 1][m] = av.y;
            AsT[kc + 2][m] = av.z; AsT[kc + 3][m] = av.w;
        }
        {
            int kr = t >> 3, nc = (t & 7) << 2;
            float4 bv = *(const float4*)(B + (size_t)(k0 + kr) * ldb + n0 + nc);
            Bs[kr][nc + 0] = bv.x; Bs[kr][nc + 1] = bv.y;
            Bs[kr][nc + 2] = bv.z; Bs[kr][nc + 3] = bv.w;
        }
        __syncthreads();
        #pragma unroll
        for (int kk = 0; kk < 32; ++kk) {
            ulonglong2 a01 = *(const ulonglong2*)&AsT[kk][tg * 8];
            ulonglong2 a23 = *(const ulonglong2*)&AsT[kk][tg * 8 + 4];
            unsigned long long b2 = dup2(Bs[kk][tn]);
            fma2(acc2[0], a01.x, b2);
            fma2(acc2[1], a01.y, b2);
            fma2(acc2[2], a23.x, b2);
            fma2(acc2[3], a23.y, b2);
        }
        __syncthreads();
    }
    unpack2(acc2[0], acc[0], acc[1]);
    unpack2(acc2[1], acc[2], acc[3]);
    unpack2(acc2[2], acc[4], acc[5]);
    unpack2(acc2[3], acc[6], acc[7]);
}

__global__ __launch_bounds__(256) void attnv_kernel(
    const float* __restrict__ scores, const float* __restrict__ nq,
    float* __restrict__ ao) {
    const int z = blockIdx.z, b = z >> 3, h = z & 7;
    const float* A = scores + (size_t)z * NN * NN;
    const float* B = nq + (size_t)b * NN * DD + h * 32;
    float acc[8];
    const int m0 = blockIdx.x * 64;
    gemm_tile64x32(A, B, NN, DD, NN, m0, 0, acc);
    const int tn = threadIdx.x & 31, tg = threadIdx.x >> 5;
    #pragma unroll
    for (int q = 0; q < 8; ++q)
        ao[((size_t)b * NN + (m0 + tg * 8 + q)) * DD + h * 32 + tn] = acc[q];
}

// ---------------- softmax (last dim 256, in place) ----------------
__global__ void softmax_kernel(float* __restrict__ sc) {
    __shared__ float sh[8];
    __shared__ float red;
    const size_t row = blockIdx.x;
    const int t = threadIdx.x;
    float v = sc[row * NN + t];
    float m = v;
    #pragma unroll
    for (int o = 16; o; o >>= 1) m = fmaxf(m, __shfl_xor_sync(0xffffffffu, m, o));
    if ((t & 31) == 0) sh[t >> 5] = m;
    __syncthreads();
    if (t == 0) {
        float mm = sh[0];
        #pragma unroll
        for (int w = 1; w < 8; ++w) mm = fmaxf(mm, sh[w]);
        red = mm;
    }
    __syncthreads();
    m = red;
    float e = expf(v - m);
    float s = e;
    #pragma unroll
    for (int o = 16; o; o >>= 1) s += __shfl_xor_sync(0xffffffffu, s, o);
    __syncthreads();
    if ((t & 31) == 0) sh[t >> 5] = s;
    __syncthreads();
    if (t == 0) {
        float ss = 0.f;
        #pragma unroll
        for (int w = 0; w < 8; ++w) ss += sh[w];
        red = 1.0f / ss;
    }
    __syncthreads();
    sc[row * NN + t] = e * red;
}

extern "C" void kernel_launch(void* const* d_in, const int* in_sizes, int n_in,
                              void* d_out, int out_size) {
    const float* nodes = (const float*)d_in[0];
    const float* edges = (const float*)d_in[1];
    const float* W     = (const float*)d_in[2];
    const float* b     = (const float*)d_in[3];
    const float* ln_g  = (const float*)d_in[4];
    const float* ln_b  = (const float*)d_in[5];
    const float* W1    = (const float*)d_in[6];
    const float* b1    = (const float*)d_in[7];
    const float* W2    = (const float*)d_in[8];
    const float* b2    = (const float*)d_in[9];
    float* out = (float*)d_out;

    float *px, *pnq, *psc, *pao, *pr, *px2, *phg;
    __half *pwq, *pw1q, *pw2q;
    cudaGetSymbolAddress((void**)&px,  g_x);
    cudaGetSymbolAddress((void**)&pnq, g_nq);
    cudaGetSymbolAddress((void**)&psc, g_sc);
    cudaGetSymbolAddress((void**)&pao, g_ao);
    cudaGetSymbolAddress((void**)&pr,  g_r);
    cudaGetSymbolAddress((void**)&px2, g_x2);
    cudaGetSymbolAddress((void**)&phg, g_hg);
    cudaGetSymbolAddress((void**)&pwq, g_wq);
    cudaGetSymbolAddress((void**)&pw1q, g_w1q);
    cudaGetSymbolAddress((void**)&pw2q, g_w2q);

    cudaFuncSetAttribute(edge_mma_kernel,
                         cudaFuncAttributeMaxDynamicSharedMemorySize, EDGE_SMEM);
    cudaFuncSetAttribute(gemm_mma32,
                         cudaFuncAttributeMaxDynamicSharedMemorySize, GM_SMEM);

    prep_pack<<<64, 256>>>(W,  pwq,  256,  16384);
    prep_pack<<<256, 256>>>(W1, pw1q, 1024, 65536);
    prep_pack<<<256, 256>>>(W2, pw2q, 256,  65536);
    ln_kernel<<<NB * NN, 256>>>(nodes, ln_g, ln_b, px);
    gemm_mma32<<<dim3(2, 16), 64, GM_SMEM>>>(px, pwq, b, nullptr, pnq, 256, 256, 0);
    edge_mma_kernel<<<dim3(8, NN, NB), 128, EDGE_SMEM>>>(edges, pwq, b, pnq, psc);
    softmax_kernel<<<NB * NH * NN, 256>>>(psc);
    attnv_kernel<<<dim3(4, 1, NB * NH), 256>>>(psc, pnq, pao);
    gemm_mma32<<<dim3(2, 16), 64, GM_SMEM>>>(pao, pwq, b, px, pr, 256, 256, 1);
    ln_kernel<<<NB * NN, 256>>>(pr, ln_g, ln_b, px2);
    gemm_mma32<<<dim3(8, 16), 64, GM_SMEM>>>(px2, pw1q, b1, nullptr, phg, 1024, 256, 2);
    gemm_mma32<<<dim3(2, 16), 64, GM_SMEM>>>(phg, pw2q, b2, px2, out, 256, 1024, 1);
}